// round 15
// baseline (speedup 1.0000x reference)
#include <cuda_runtime.h>
#include <cuda_bf16.h>
#include <math.h>
#include <stdint.h>

#define E_N 100000
#define D_N 300
#define R_N 1000
#define T_N 10000
#define K_N 25
#define SD  320
#define D4  75
#define SD4 80
#define GAMMA_F 1.0f
#define WOFF (320*320)
#define NNZ_ADJ 600000
#define NNZ_ER  300000

// ---------------- scratch (device globals: allocation-free) ----------------
__device__ float g_emb[(size_t)E_N * SD];
__device__ float g_A1 [(size_t)E_N * SD];
__device__ float g_A2 [(size_t)E_N * SD];
__device__ float g_A3 [(size_t)E_N * SD];
__device__ float g_A5 [(size_t)E_N * SD];
__device__ float g_A6 [(size_t)E_N * SD];
__device__ float g_Lm [R_N * SD];
__device__ float g_Rm [R_N * SD];
__device__ float g_P  [R_N * SD];
__device__ float g_Wt [2 * SD * SD];
__device__ __nv_bfloat16 g_Bh[(size_t)E_N * SD];  // split pair A (emb, then hg1)
__device__ __nv_bfloat16 g_Bl[(size_t)E_N * SD];
__device__ __nv_bfloat16 g_Ch[(size_t)E_N * SD];  // split pair B (h)
__device__ __nv_bfloat16 g_Cl[(size_t)E_N * SD];
__device__ __nv_bfloat16 g_WTh[4 * WOFF];         // transposed weights hi: 0:Dt 1:W1 2:W2 3:KG
__device__ __nv_bfloat16 g_WTl[4 * WOFF];
// CSR scratch
__device__ int g_adj_ptr[E_N + 1];
__device__ int g_adj_cur[E_N];
__device__ int g_adj_perm[NNZ_ADJ];
__device__ int g_er_ptr[E_N + 1];
__device__ int g_er_cur[E_N];
__device__ int g_er_perm[NNZ_ER];
__device__ int g_bsum[256];

// ---------------- helpers ----------------
__device__ __forceinline__ uint32_t smem_to_u32(const void* p) {
    uint32_t a;
    asm("{ .reg .u64 t; cvta.to.shared.u64 t, %1; cvt.u32.u64 %0, t; }" : "=r"(a) : "l"(p));
    return a;
}
__device__ __forceinline__ float warp_sum(float v) {
#pragma unroll
    for (int o = 16; o > 0; o >>= 1) v += __shfl_xor_sync(0xffffffffu, v, o);
    return v;
}
__device__ __forceinline__ int warp_sum_i(int v) {
#pragma unroll
    for (int o = 16; o > 0; o >>= 1) v += __shfl_xor_sync(0xffffffffu, v, o);
    return v;
}
__device__ __forceinline__ unsigned long long bcast2(float x) {
    unsigned long long r;
    asm("mov.b64 %0, {%1, %1};" : "=l"(r) : "f"(x));
    return r;
}
__device__ __forceinline__ float2 unpack2(unsigned long long v) {
    float2 f;
    asm("mov.b64 {%0, %1}, %2;" : "=f"(f.x), "=f"(f.y) : "l"(v));
    return f;
}
__device__ __forceinline__ void ffma2(unsigned long long& d, unsigned long long a, unsigned long long b) {
    asm("fma.rn.f32x2 %0, %1, %2, %0;" : "+l"(d) : "l"(a), "l"(b));
}
__device__ __forceinline__ void red_add_v4(float* p, float a, float b, float c, float d) {
    asm volatile("red.global.add.v4.f32 [%0], {%1, %2, %3, %4};"
                 :: "l"(p), "f"(a), "f"(b), "f"(c), "f"(d) : "memory");
}
__device__ __forceinline__ void cp16(uint32_t dst, const void* src, int src_bytes) {
    asm volatile("cp.async.cg.shared.global [%0], [%1], 16, %2;"
                 :: "r"(dst), "l"(src), "r"(src_bytes) : "memory");
}
#define CP_COMMIT() asm volatile("cp.async.commit_group;" ::: "memory")
template <int N>
__device__ __forceinline__ void cp_wait() {
    asm volatile("cp.async.wait_group %0;" :: "n"(N) : "memory");
}
__device__ __forceinline__ void ldsm4(uint32_t* r, uint32_t addr) {
    asm volatile("ldmatrix.sync.aligned.m8n8.x4.shared.b16 {%0,%1,%2,%3}, [%4];"
                 : "=r"(r[0]), "=r"(r[1]), "=r"(r[2]), "=r"(r[3]) : "r"(addr));
}
__device__ __forceinline__ void mma16816(float* d, const uint32_t* a, uint32_t b0, uint32_t b1) {
    asm volatile("mma.sync.aligned.m16n8k16.row.col.f32.bf16.bf16.f32 "
                 "{%0,%1,%2,%3}, {%4,%5,%6,%7}, {%8,%9}, {%0,%1,%2,%3};"
                 : "+f"(d[0]), "+f"(d[1]), "+f"(d[2]), "+f"(d[3])
                 : "r"(a[0]), "r"(a[1]), "r"(a[2]), "r"(a[3]), "r"(b0), "r"(b1));
}
__device__ __forceinline__ void split2(float v, __nv_bfloat16& h, __nv_bfloat16& l) {
    h = __float2bfloat16_rn(v);
    l = __float2bfloat16_rn(v - __bfloat162float(h));
}

// ---------------- CSR build kernels ----------------
__global__ void zcnt_kernel(int* cnt, int n) {
    int i = blockIdx.x * blockDim.x + threadIdx.x;
    if (i < n) cnt[i] = 0;
}
__global__ void hist_kernel(const int* __restrict__ rows, int nnz, int* cnt) {
    int i = blockIdx.x * blockDim.x + threadIdx.x;
    if (i < nnz) atomicAdd(&cnt[rows[i]], 1);
}
__global__ void scan1_kernel(const int* __restrict__ cnt, int n, int* bsum) {
    __shared__ int sh[8];
    int t = threadIdx.x, base = blockIdx.x * 1024 + t * 4;
    int s = 0;
#pragma unroll
    for (int q = 0; q < 4; q++) if (base + q < n) s += cnt[base + q];
    s = warp_sum_i(s);
    if ((t & 31) == 0) sh[t >> 5] = s;
    __syncthreads();
    if (t == 0) {
        int tot = 0;
#pragma unroll
        for (int w = 0; w < 8; w++) tot += sh[w];
        bsum[blockIdx.x] = tot;
    }
}
__global__ void scan2_kernel(int* bsum, int nb) {
    if (threadIdx.x == 0 && blockIdx.x == 0) {
        int run = 0;
        for (int i = 0; i < nb; i++) { int v = bsum[i]; bsum[i] = run; run += v; }
    }
}
__global__ void scan3_kernel(const int* __restrict__ cnt, const int* __restrict__ bsum,
                             int n, int* rowptr, int* cursor) {
    __shared__ int ts[256];
    int t = threadIdx.x, b = blockIdx.x;
    int base = b * 1024 + t * 4;
    int v[4], s = 0;
#pragma unroll
    for (int q = 0; q < 4; q++) { v[q] = (base + q < n) ? cnt[base + q] : 0; s += v[q]; }
    ts[t] = s;
    __syncthreads();
#pragma unroll
    for (int off = 1; off < 256; off <<= 1) {
        int x = (t >= off) ? ts[t - off] : 0;
        __syncthreads();
        ts[t] += x;
        __syncthreads();
    }
    int pre = bsum[b] + (t ? ts[t - 1] : 0);
#pragma unroll
    for (int q = 0; q < 4; q++) {
        int i = base + q;
        if (i < n) {
            rowptr[i] = pre;
            cursor[i] = pre;
            pre += v[q];
            if (i == n - 1) rowptr[n] = pre;
        }
    }
}
__global__ void scatter_kernel(const int* __restrict__ rows, int nnz, int* cursor, int* perm) {
    int i = blockIdx.x * blockDim.x + threadIdx.x;
    if (i < nnz) {
        int pos = atomicAdd(&cursor[rows[i]], 1);
        perm[pos] = i;
    }
}

// ---------------- small kernels ----------------
__global__ void zero_out_kernel(float* out) { if (threadIdx.x == 0 && blockIdx.x == 0) out[0] = 0.0f; }

__global__ void zero4_kernel(float4* p, int n4) {
    int i = blockIdx.x * blockDim.x + threadIdx.x;
    if (i < n4) p[i] = make_float4(0.f, 0.f, 0.f, 0.f);
}

__global__ void pad_weights_kernel(const float* __restrict__ Dense) {
    int idx = blockIdx.x * blockDim.x + threadIdx.x;
    if (idx >= 2 * SD * SD) return;
    int w = idx / (SD * SD);
    int rem = idx % (SD * SD);
    int r = rem / SD, c = rem % SD;
    float v = 0.f;
    if (r < D_N && c < D_N) v = Dense[(size_t)(D_N * (1 + w) + r) * D_N + c];
    g_Wt[idx] = v;
}

__global__ void wsplit_kernel(const float* __restrict__ Dense, const float* __restrict__ W1,
                              const float* __restrict__ W2, const float* __restrict__ KG) {
    int idx = blockIdx.x * blockDim.x + threadIdx.x;
    if (idx >= 4 * WOFF) return;
    int w = idx / WOFF;
    int rem = idx % WOFF;
    int n = rem / 320, k = rem % 320;
    float v = 0.f;
    if (n < D_N && k < D_N) {
        const float* src = (w == 0) ? Dense : (w == 1) ? W1 : (w == 2) ? W2 : KG;
        v = src[(size_t)k * D_N + n];
    }
    __nv_bfloat16 hi, lo;
    split2(v, hi, lo);
    g_WTh[idx] = hi;
    g_WTl[idx] = lo;
}

// normalize + emb splits (to Bh/Bl). Warp per row.
__global__ void normalize_kernel(const float* __restrict__ we) {
    int warp = (blockIdx.x * blockDim.x + threadIdx.x) >> 5;
    int lane = threadIdx.x & 31;
    if (warp >= E_N) return;
    const float4* src = (const float4*)(we + (size_t)warp * D_N);
    float4 v[3];
    float s = 0.f;
#pragma unroll
    for (int it = 0; it < 3; it++) {
        int j = lane + it * 32;
        if (j < D4) {
            float4 x = src[j];
            v[it] = x;
            s += x.x * x.x + x.y * x.y + x.z * x.z + x.w * x.w;
        } else v[it] = make_float4(0.f, 0.f, 0.f, 0.f);
    }
    s = warp_sum(s);
    float inv = 1.0f / sqrtf(s);
    float4* dst = (float4*)(g_emb + (size_t)warp * SD);
    __nv_bfloat162* bh = (__nv_bfloat162*)(g_Bh + (size_t)warp * SD);
    __nv_bfloat162* bl = (__nv_bfloat162*)(g_Bl + (size_t)warp * SD);
#pragma unroll
    for (int it = 0; it < 3; it++) {
        int j = lane + it * 32;
        if (j < SD4) {
            float4 o = make_float4(0.f, 0.f, 0.f, 0.f);
            if (j < D4) o = make_float4(v[it].x * inv, v[it].y * inv, v[it].z * inv, v[it].w * inv);
            dst[j] = o;
            float xs[4] = {o.x, o.y, o.z, o.w};
            __nv_bfloat16 h[4], l[4];
#pragma unroll
            for (int q = 0; q < 4; q++) split2(xs[q], h[q], l[q]);
            __nv_bfloat162 h0, h1, l0, l1;
            h0.x = h[0]; h0.y = h[1]; h1.x = h[2]; h1.y = h[3];
            l0.x = l[0]; l0.y = l[1]; l1.x = l[2]; l1.y = l[3];
            bh[2 * j] = h0; bh[2 * j + 1] = h1;
            bl[2 * j] = l0; bl[2 * j + 1] = l1;
        }
    }
}

// COO SpMM scatter (hr/tr only). Warp per nnz.
__global__ void spmm_kernel(const int* __restrict__ rows, const int* __restrict__ cols,
                            const float* __restrict__ vals, int nnz,
                            const float* __restrict__ X, float* __restrict__ Out) {
    int warp = (blockIdx.x * blockDim.x + threadIdx.x) >> 5;
    int lane = threadIdx.x & 31;
    if (warp >= nnz) return;
    int   r = rows[warp];
    int   c = cols[warp];
    float v = vals[warp];
    const float4* xr = (const float4*)(X + (size_t)c * SD);
    float* orow = Out + (size_t)r * SD;
#pragma unroll
    for (int it = 0; it < 3; it++) {
        int j = lane + it * 32;
        if (j < D4) {
            float4 x = xr[j];
            red_add_v4(orow + j * 4, v * x.x, v * x.y, v * x.z, v * x.w);
        }
    }
}

// CSR gather SpMM, column slice [col0, col0 + n4*4): warp per output row, no atomics.
// Two passes keep the per-pass working set (~64 MB) inside L2 so the degree-6 reuse hits.
__global__ void gspmm_kernel(const int* __restrict__ rowptr, const int* __restrict__ perm,
                             const int* __restrict__ cols, const float* __restrict__ vals,
                             const float* __restrict__ X, float* __restrict__ Out,
                             int n_rows, int col0, int n4) {
    int warp = (blockIdx.x * blockDim.x + threadIdx.x) >> 5;
    int lane = threadIdx.x & 31;
    if (warp >= n_rows) return;
    int s = rowptr[warp], e = rowptr[warp + 1];
    int extra = n4 - 32;                 // lanes < extra handle a 2nd float4
    float4 a0 = make_float4(0.f, 0.f, 0.f, 0.f);
    float4 a1 = a0;
    const float* base = X + col0;
    for (int idx = s; idx < e; idx++) {
        int i = perm[idx];
        int c = cols[i];
        float v = vals[i];
        const float4* xr = (const float4*)(base + (size_t)c * SD);
        float4 x0 = xr[lane];
        a0.x += v * x0.x; a0.y += v * x0.y; a0.z += v * x0.z; a0.w += v * x0.w;
        if (lane < extra) {
            float4 x1 = xr[lane + 32];
            a1.x += v * x1.x; a1.y += v * x1.y; a1.z += v * x1.z; a1.w += v * x1.w;
        }
    }
    float4* o = (float4*)(Out + (size_t)warp * SD + col0);
    o[lane] = a0;
    if (lane < extra) o[lane + 32] = a1;
}

// Fused: h = emb + relu(A1 + er_gather(+-P) + Bias); writes h -> A2 and splits -> Ch/Cl.
__global__ void h_er_kernel(const int* __restrict__ rowptr, const int* __restrict__ perm,
                            const int* __restrict__ cols, const float* __restrict__ vals,
                            const float* __restrict__ Bias) {
    int warp = (blockIdx.x * blockDim.x + threadIdx.x) >> 5;
    int lane = threadIdx.x & 31;
    if (warp >= E_N) return;
    const float4* pr = (const float4*)(g_A1 + (size_t)warp * SD);
    float4 a0 = pr[lane], a1 = pr[lane + 32];
    float4 a2 = make_float4(0.f, 0.f, 0.f, 0.f);
    if (lane < 11) a2 = pr[lane + 64];
    int s = rowptr[warp], e = rowptr[warp + 1];
    for (int idx = s; idx < e; idx++) {
        int i = perm[idx];
        int c = cols[i];
        float v = vals[i];
        if (c >= R_N) { c -= R_N; v = -v; }
        const float4* xr = (const float4*)(g_P + (size_t)c * SD);
        float4 x0 = xr[lane], x1 = xr[lane + 32];
        a0.x += v * x0.x; a0.y += v * x0.y; a0.z += v * x0.z; a0.w += v * x0.w;
        a1.x += v * x1.x; a1.y += v * x1.y; a1.z += v * x1.z; a1.w += v * x1.w;
        if (lane < 11) {
            float4 x2 = xr[lane + 64];
            a2.x += v * x2.x; a2.y += v * x2.y; a2.z += v * x2.z; a2.w += v * x2.w;
        }
    }
    const float4* er = (const float4*)(g_emb + (size_t)warp * SD);
    float4* ho = (float4*)(g_A2 + (size_t)warp * SD);
    __nv_bfloat162* ch = (__nv_bfloat162*)(g_Ch + (size_t)warp * SD);
    __nv_bfloat162* cl = (__nv_bfloat162*)(g_Cl + (size_t)warp * SD);
    float4 accs[3] = {a0, a1, a2};
#pragma unroll
    for (int it = 0; it < 3; it++) {
        int j = lane + it * 32;
        if (j >= SD4) continue;
        float4 o = make_float4(0.f, 0.f, 0.f, 0.f);
        if (j < D4) {
            float4 em = er[j];
            float4 a = accs[it];
            int d = j * 4;
            o.x = em.x + fmaxf(a.x + Bias[d + 0], 0.f);
            o.y = em.y + fmaxf(a.y + Bias[d + 1], 0.f);
            o.z = em.z + fmaxf(a.z + Bias[d + 2], 0.f);
            o.w = em.w + fmaxf(a.w + Bias[d + 3], 0.f);
        }
        ho[j] = o;
        float xs[4] = {o.x, o.y, o.z, o.w};
        __nv_bfloat16 h[4], l[4];
#pragma unroll
        for (int q = 0; q < 4; q++) split2(xs[q], h[q], l[q]);
        __nv_bfloat162 h0, h1, l0, l1;
        h0.x = h[0]; h0.y = h[1]; h1.x = h[2]; h1.y = h[3];
        l0.x = l[0]; l0.y = l[1]; l1.x = l[2]; l1.y = l[3];
        ch[2 * j] = h0; ch[2 * j + 1] = h1;
        cl[2 * j] = l0; cl[2 * j + 1] = l1;
    }
}

// ---------------- HMMA GEMM (bf16 split-2): C[M,320] = X @ W ----------------
#define MMN 160
#define MMK 32
#define MMS 40
#define A_TB (128 * MMS * 2)
#define B_TB (MMN * MMS * 2)
#define MM_STAGE (2 * A_TB + 2 * B_TB)
#define MM_SMEM  (2 * MM_STAGE)
#define MM_CH 10

__device__ __forceinline__ void mm_load_stage(uint32_t sb,
                                              const __nv_bfloat16* Xh, const __nv_bfloat16* Xl,
                                              const __nv_bfloat16* Wh, const __nv_bfloat16* Wl,
                                              int bm, int bn, int M, int k0, int tid) {
#pragma unroll
    for (int q = 0; q < 9; q++) {
        int idx = q * 256 + tid;
        if (idx < 1024) {
            int part = idx >> 9;
            int r = (idx & 511) >> 2, c = idx & 3;
            const __nv_bfloat16* src = (part ? Xl : Xh) + (size_t)(bm + r) * 320 + k0 + c * 8;
            int ok = (bm + r < M) ? 16 : 0;
            cp16(sb + part * A_TB + r * (MMS * 2) + c * 16, src, ok);
        } else if (idx < 2304) {
            int t = idx - 1024;
            int part = t >= 640 ? 1 : 0;
            int rr = t - part * 640;
            int r = rr >> 2, c = rr & 3;
            const __nv_bfloat16* src = (part ? Wl : Wh) + (size_t)(bn + r) * 320 + k0 + c * 8;
            cp16(sb + 2 * A_TB + part * B_TB + r * (MMS * 2) + c * 16, src, 16);
        }
    }
    CP_COMMIT();
}

__global__ __launch_bounds__(256, 2) void mgemm_kernel(const __nv_bfloat16* __restrict__ Xh,
                                                       const __nv_bfloat16* __restrict__ Xl,
                                                       const __nv_bfloat16* __restrict__ Wh,
                                                       const __nv_bfloat16* __restrict__ Wl,
                                                       float* __restrict__ C, int M, int mode,
                                                       const float* __restrict__ ep1,
                                                       const float* __restrict__ ep2,
                                                       const float* __restrict__ epv,
                                                       __nv_bfloat16* __restrict__ Oh,
                                                       __nv_bfloat16* __restrict__ Ol) {
    extern __shared__ char sm8[];
    uint32_t smb = smem_to_u32(sm8);
    int tid = threadIdx.x, wid = tid >> 5, lane = tid & 31;
    int bn = blockIdx.x * MMN, bm = blockIdx.y * 128;
    int wm = (wid >> 1) * 32;
    int wn = (wid & 1) * 80;

    float acc[2][10][4];
#pragma unroll
    for (int i = 0; i < 2; i++)
#pragma unroll
        for (int j = 0; j < 10; j++)
#pragma unroll
            for (int q = 0; q < 4; q++) acc[i][j][q] = 0.f;

    int aRow = lane & 15, aKsel = (lane >> 4) * 8;
    int bRow = (lane >> 4) * 8 + (lane & 7), bKsel = ((lane >> 3) & 1) * 8;

    mm_load_stage(smb, Xh, Xl, Wh, Wl, bm, bn, M, 0, tid);

    for (int ch = 0; ch < MM_CH; ch++) {
        uint32_t sb = smb + (ch & 1) * MM_STAGE;
        if (ch + 1 < MM_CH)
            mm_load_stage(smb + ((ch + 1) & 1) * MM_STAGE, Xh, Xl, Wh, Wl, bm, bn, M, (ch + 1) * MMK, tid);
        if (ch + 1 < MM_CH) cp_wait<1>(); else cp_wait<0>();
        __syncthreads();
#pragma unroll
        for (int ks = 0; ks < 2; ks++) {
            // K = 304 suffices: k >= 304 is provably zero in both operands
            if (ks == 1 && ch == MM_CH - 1) continue;
            int k0 = ks * 16;
            uint32_t ah[2][4], al[2][4];
#pragma unroll
            for (int i = 0; i < 2; i++) {
                uint32_t ad = sb + ((wm + i * 16 + aRow) * MMS + k0 + aKsel) * 2;
                ldsm4(ah[i], ad);
                ldsm4(al[i], ad + A_TB);
            }
#pragma unroll
            for (int j = 0; j < 5; j++) {
                uint32_t bh[4], bl[4];
                uint32_t bd = sb + 2 * A_TB + ((wn + j * 16 + bRow) * MMS + k0 + bKsel) * 2;
                ldsm4(bh, bd);
                ldsm4(bl, bd + B_TB);
#pragma unroll
                for (int i = 0; i < 2; i++)
#pragma unroll
                    for (int t = 0; t < 2; t++) {
                        float* a4 = acc[i][j * 2 + t];
                        mma16816(a4, ah[i], bh[t * 2], bh[t * 2 + 1]);
                        mma16816(a4, ah[i], bl[t * 2], bl[t * 2 + 1]);
                        mma16816(a4, al[i], bh[t * 2], bh[t * 2 + 1]);
                    }
            }
        }
        __syncthreads();
    }

#pragma unroll
    for (int i = 0; i < 2; i++)
#pragma unroll
        for (int jj = 0; jj < 10; jj++) {
            int col = bn + wn + jj * 8 + (lane & 3) * 2;
#pragma unroll
            for (int half = 0; half < 2; half++) {
                int row = bm + wm + i * 16 + (lane >> 2) + half * 8;
                if (row >= M) continue;
                float v0 = acc[i][jj][half * 2], v1 = acc[i][jj][half * 2 + 1];
                float* crow = C + (size_t)row * SD + col;
                if (mode == 0) {
                    *(float2*)crow = make_float2(v0, v1);
                } else {
                    const float* l1 = ep1 + (size_t)row * SD + col;
                    const float* gc = ep2 + (size_t)row * SD + col;
                    float2 a = *(const float2*)l1;
                    float2 g = *(const float2*)gc;
                    float o0 = 0.f, o1 = 0.f;
                    if (col < D_N) {
                        float tg = 1.0f / (1.0f + expf(-(v0 + epv[col])));
                        o0 = tg * fmaxf(g.x, 0.f) + (1.0f - tg) * a.x;
                    }
                    if (col + 1 < D_N) {
                        float tg = 1.0f / (1.0f + expf(-(v1 + epv[col + 1])));
                        o1 = tg * fmaxf(g.y, 0.f) + (1.0f - tg) * a.y;
                    }
                    *(float2*)crow = make_float2(o0, o1);
                    if (mode == 4) {
                        __nv_bfloat16 h0, h1, l0, l1b;
                        split2(o0, h0, l0);
                        split2(o1, h1, l1b);
                        __nv_bfloat162 hh, ll;
                        hh.x = h0; hh.y = h1;
                        ll.x = l0; ll.y = l1b;
                        *(__nv_bfloat162*)(Oh + (size_t)row * SD + col) = hh;
                        *(__nv_bfloat162*)(Ol + (size_t)row * SD + col) = ll;
                    }
                }
            }
        }
}

// ---------------- FFMA2 SGEMM (small R_N GEMMs) ----------------
#define BM 256
#define BN 64
#define BK 16
#define KTILES 19
__global__ __launch_bounds__(256, 2) void sgemm_kernel(const float* __restrict__ A,
                                                       const float* __restrict__ B,
                                                       float* __restrict__ C,
                                                       int M, int accumulate) {
    __shared__ float As[2][BK][BM];
    __shared__ float Bs[2][BK][BN];
    int bm = blockIdx.y * BM;
    int bn = blockIdx.x * BN;
    int tid = threadIdx.x;
    int tx = tid & 7;
    int ty = tid >> 3;
    int arow = bm + tid;
    bool avalid = arow < M;
    const float* Aptr = A + (size_t)arow * SD;
    int brow  = tid >> 4;
    int bcol4 = tid & 15;
    const float* Bptr = B + (size_t)brow * SD + bn + bcol4 * 4;

    unsigned long long acc[8][4];
#pragma unroll
    for (int i = 0; i < 8; i++)
#pragma unroll
        for (int j = 0; j < 4; j++) acc[i][j] = 0ull;

    float4 ra[4], rb;
#pragma unroll
    for (int c = 0; c < 4; c++)
        ra[c] = avalid ? *(const float4*)(Aptr + c * 4) : make_float4(0.f, 0.f, 0.f, 0.f);
    rb = *(const float4*)(Bptr);
#pragma unroll
    for (int c = 0; c < 4; c++) {
        As[0][c * 4 + 0][tid] = ra[c].x;
        As[0][c * 4 + 1][tid] = ra[c].y;
        As[0][c * 4 + 2][tid] = ra[c].z;
        As[0][c * 4 + 3][tid] = ra[c].w;
    }
    *(float4*)(&Bs[0][brow][bcol4 * 4]) = rb;
    __syncthreads();

    for (int t = 0; t < KTILES; t++) {
        int cur = t & 1, nxt = cur ^ 1;
        if (t + 1 < KTILES) {
            int k0 = (t + 1) * BK;
#pragma unroll
            for (int c = 0; c < 4; c++)
                ra[c] = avalid ? *(const float4*)(Aptr + k0 + c * 4) : make_float4(0.f, 0.f, 0.f, 0.f);
            rb = *(const float4*)(Bptr + (size_t)k0 * SD);
        }
#pragma unroll
        for (int k = 0; k < BK; k++) {
            ulonglong2 bb0 = *(const ulonglong2*)(&Bs[cur][k][tx * 8]);
            ulonglong2 bb1 = *(const ulonglong2*)(&Bs[cur][k][tx * 8 + 4]);
            unsigned long long b2[4] = {bb0.x, bb0.y, bb1.x, bb1.y};
            float4 a0 = *(const float4*)(&As[cur][k][ty * 8]);
            float4 a1 = *(const float4*)(&As[cur][k][ty * 8 + 4]);
            unsigned long long a2[8];
            a2[0] = bcast2(a0.x); a2[1] = bcast2(a0.y); a2[2] = bcast2(a0.z); a2[3] = bcast2(a0.w);
            a2[4] = bcast2(a1.x); a2[5] = bcast2(a1.y); a2[6] = bcast2(a1.z); a2[7] = bcast2(a1.w);
#pragma unroll
            for (int i = 0; i < 8; i++)
#pragma unroll
                for (int j = 0; j < 4; j++)
                    ffma2(acc[i][j], a2[i], b2[j]);
        }
        if (t + 1 < KTILES) {
#pragma unroll
            for (int c = 0; c < 4; c++) {
                As[nxt][c * 4 + 0][tid] = ra[c].x;
                As[nxt][c * 4 + 1][tid] = ra[c].y;
                As[nxt][c * 4 + 2][tid] = ra[c].z;
                As[nxt][c * 4 + 3][tid] = ra[c].w;
            }
            *(float4*)(&Bs[nxt][brow][bcol4 * 4]) = rb;
        }
        __syncthreads();
    }

    int gcol = bn + tx * 8;
#pragma unroll
    for (int i = 0; i < 8; i++) {
        int grow = bm + ty * 8 + i;
        if (grow >= M) continue;
        float2 u0 = unpack2(acc[i][0]);
        float2 u1 = unpack2(acc[i][1]);
        float2 u2 = unpack2(acc[i][2]);
        float2 u3 = unpack2(acc[i][3]);
        float* crow = C + (size_t)grow * SD + gcol;
        if (accumulate) {
            float4 c0 = *(float4*)crow;
            float4 c1 = *(float4*)(crow + 4);
            *(float4*)crow       = make_float4(c0.x + u0.x, c0.y + u0.y, c0.z + u1.x, c0.w + u1.y);
            *(float4*)(crow + 4) = make_float4(c1.x + u2.x, c1.y + u2.y, c1.z + u3.x, c1.w + u3.y);
        } else {
            *(float4*)crow       = make_float4(u0.x, u0.y, u1.x, u1.y);
            *(float4*)(crow + 4) = make_float4(u2.x, u2.y, u3.x, u3.y);
        }
    }
}

// Fused hinge loss: one block per pair t.
__global__ __launch_bounds__(256) void loss_kernel(const int* __restrict__ pl,
                                                   const int* __restrict__ pr,
                                                   const int* __restrict__ nr,
                                                   const int* __restrict__ nl,
                                                   const float* __restrict__ mask,
                                                   const float* __restrict__ node,
                                                   float* __restrict__ out) {
    __shared__ float4 sl[D4], sr[D4];
    __shared__ float wpart[8];
    __shared__ float s_dm;
    int t    = blockIdx.x;
    int tid  = threadIdx.x;
    int lane = tid & 31;
    int wid  = tid >> 5;

    const float4* xl = (const float4*)(node + (size_t)pl[t] * SD);
    const float4* xr = (const float4*)(node + (size_t)pr[t] * SD);
    float d = 0.f;
    if (tid < D4) {
        float4 a = xl[tid], b = xr[tid];
        sl[tid] = a; sr[tid] = b;
        d = fabsf(a.x - b.x) + fabsf(a.y - b.y) + fabsf(a.z - b.z) + fabsf(a.w - b.w);
    }
    d = warp_sum(d);
    if (lane == 0) wpart[wid] = d;
    __syncthreads();
    if (tid == 0) s_dm = wpart[0] + wpart[1] + wpart[2] + GAMMA_F;
    __syncthreads();
    float dm = s_dm;

    float hsum = 0.f;
    for (int k = wid; k < K_N; k += 8) {
        int i = t * K_N + k;
        const float4* xR = (const float4*)(node + (size_t)nr[i] * SD);
        const float4* xL = (const float4*)(node + (size_t)nl[i] * SD);
        float s1 = 0.f, s2 = 0.f;
#pragma unroll
        for (int it = 0; it < 3; it++) {
            int j = lane + it * 32;
            if (j < D4) {
                float4 a = sl[j], b = sr[j], cr = xR[j], cl = xL[j];
                s1 += fabsf(a.x - cr.x) + fabsf(a.y - cr.y) + fabsf(a.z - cr.z) + fabsf(a.w - cr.w);
                s2 += fabsf(cl.x - b.x) + fabsf(cl.y - b.y) + fabsf(cl.z - b.z) + fabsf(cl.w - b.w);
            }
        }
        s1 = warp_sum(s1);
        s2 = warp_sum(s2);
        if (lane == 0) hsum += (fmaxf(dm - s1, 0.f) + fmaxf(dm - s2, 0.f)) * mask[i];
    }
    if (lane == 0) wpart[wid] = hsum;
    __syncthreads();
    if (tid == 0) {
        float tot = 0.f;
#pragma unroll
        for (int w = 0; w < 8; w++) tot += wpart[w];
        atomicAdd(out, tot * 0.5f);
    }
}

// ---------------- host ----------------
extern "C" void kernel_launch(void* const* d_in, const int* in_sizes, int n_in,
                              void* d_out, int out_size) {
    const float* we    = (const float*)d_in[0];
    const float* kgw   = (const float*)d_in[1];
    const float* bg    = (const float*)d_in[2];
    const float* W1    = (const float*)d_in[3];
    const float* W2    = (const float*)d_in[4];
    const float* Dense = (const float*)d_in[5];
    const float* Bias  = (const float*)d_in[6];
    const int*   hr_rows = (const int*)d_in[7];
    const int*   hr_cols = (const int*)d_in[8];
    const float* hr_vals = (const float*)d_in[9];
    const int*   tr_rows = (const int*)d_in[10];
    const int*   tr_cols = (const int*)d_in[11];
    const float* tr_vals = (const float*)d_in[12];
    const int*   er_rows = (const int*)d_in[13];
    const int*   er_cols = (const int*)d_in[14];
    const float* er_vals = (const float*)d_in[15];
    const int*   adj_rows = (const int*)d_in[16];
    const int*   adj_cols = (const int*)d_in[17];
    const float* adj_vals = (const float*)d_in[18];
    const int*   pos_left  = (const int*)d_in[19];
    const int*   pos_right = (const int*)d_in[20];
    const int*   neg_right = (const int*)d_in[21];
    const int*   neg_left  = (const int*)d_in[22];
    const float* mask      = (const float*)d_in[23];
    float* out = (float*)d_out;

    int nnz_hr  = in_sizes[7];
    int nnz_tr  = in_sizes[10];
    int nnz_er  = in_sizes[13];
    int nnz_adj = in_sizes[16];

    float *p_emb, *p_A1, *p_A2, *p_A3, *p_A5, *p_A6, *p_Lm, *p_Rm, *p_P, *p_Wt;
    __nv_bfloat16 *p_Bh, *p_Bl, *p_Ch, *p_Cl, *p_WTh, *p_WTl;
    int *p_adj_ptr, *p_adj_cur, *p_adj_perm, *p_er_ptr, *p_er_cur, *p_er_perm, *p_bsum;
    cudaGetSymbolAddress((void**)&p_emb, g_emb);
    cudaGetSymbolAddress((void**)&p_A1,  g_A1);
    cudaGetSymbolAddress((void**)&p_A2,  g_A2);
    cudaGetSymbolAddress((void**)&p_A3,  g_A3);
    cudaGetSymbolAddress((void**)&p_A5,  g_A5);
    cudaGetSymbolAddress((void**)&p_A6,  g_A6);
    cudaGetSymbolAddress((void**)&p_Lm,  g_Lm);
    cudaGetSymbolAddress((void**)&p_Rm,  g_Rm);
    cudaGetSymbolAddress((void**)&p_P,   g_P);
    cudaGetSymbolAddress((void**)&p_Wt,  g_Wt);
    cudaGetSymbolAddress((void**)&p_Bh,  g_Bh);
    cudaGetSymbolAddress((void**)&p_Bl,  g_Bl);
    cudaGetSymbolAddress((void**)&p_Ch,  g_Ch);
    cudaGetSymbolAddress((void**)&p_Cl,  g_Cl);
    cudaGetSymbolAddress((void**)&p_WTh, g_WTh);
    cudaGetSymbolAddress((void**)&p_WTl, g_WTl);
    cudaGetSymbolAddress((void**)&p_adj_ptr,  g_adj_ptr);
    cudaGetSymbolAddress((void**)&p_adj_cur,  g_adj_cur);
    cudaGetSymbolAddress((void**)&p_adj_perm, g_adj_perm);
    cudaGetSymbolAddress((void**)&p_er_ptr,   g_er_ptr);
    cudaGetSymbolAddress((void**)&p_er_cur,   g_er_cur);
    cudaGetSymbolAddress((void**)&p_er_perm,  g_er_perm);
    cudaGetSymbolAddress((void**)&p_bsum,     g_bsum);

    cudaFuncSetAttribute(mgemm_kernel, cudaFuncAttributeMaxDynamicSharedMemorySize, MM_SMEM);

    dim3 mmGrid(SD / MMN, (E_N + 127) / 128);       // (2, 782)
    dim3 gemmGridR(SD / BN, (R_N + BM - 1) / BM);
    const int NB_E = (E_N + 1023) / 1024;           // 98
    const int GW = (E_N * 32 + 255) / 256;          // warp-per-row grids

    // 1-3, then launch #4 = first HMMA GEMM (profiled)
    wsplit_kernel<<<(4 * WOFF + 255) / 256, 256>>>(Dense, W1, W2, kgw);
    normalize_kernel<<<GW, 256>>>(we);
    zero4_kernel<<<(R_N * SD / 4 + 255) / 256, 256>>>((float4*)p_Lm, R_N * SD / 4);
    mgemm_kernel<<<mmGrid, 256, MM_SMEM>>>(p_Bh, p_Bl, p_WTh, p_WTl, p_A1, E_N, 0, 0, 0, 0, 0, 0);

    // ---- CSR build: adj ----
    zcnt_kernel<<<(E_N + 255) / 256, 256>>>(p_adj_cur, E_N);
    hist_kernel<<<(nnz_adj + 255) / 256, 256>>>(adj_rows, nnz_adj, p_adj_cur);
    scan1_kernel<<<NB_E, 256>>>(p_adj_cur, E_N, p_bsum);
    scan2_kernel<<<1, 32>>>(p_bsum, NB_E);
    scan3_kernel<<<NB_E, 256>>>(p_adj_cur, p_bsum, E_N, p_adj_ptr, p_adj_cur);
    scatter_kernel<<<(nnz_adj + 255) / 256, 256>>>(adj_rows, nnz_adj, p_adj_cur, p_adj_perm);

    // ---- CSR build: er ----
    zcnt_kernel<<<(E_N + 255) / 256, 256>>>(p_er_cur, E_N);
    hist_kernel<<<(nnz_er + 255) / 256, 256>>>(er_rows, nnz_er, p_er_cur);
    scan1_kernel<<<NB_E, 256>>>(p_er_cur, E_N, p_bsum);
    scan2_kernel<<<1, 32>>>(p_bsum, NB_E);
    scan3_kernel<<<NB_E, 256>>>(p_er_cur, p_bsum, E_N, p_er_ptr, p_er_cur);
    scatter_kernel<<<(nnz_er + 255) / 256, 256>>>(er_rows, nnz_er, p_er_cur, p_er_perm);

    // relation aggregation (scatter; small outputs)
    zero4_kernel<<<(R_N * SD / 4 + 255) / 256, 256>>>((float4*)p_Rm, R_N * SD / 4);
    spmm_kernel<<<(nnz_hr + 7) / 8, 256>>>(hr_rows, hr_cols, hr_vals, nnz_hr, p_emb, p_Lm);
    spmm_kernel<<<(nnz_tr + 7) / 8, 256>>>(tr_rows, tr_cols, tr_vals, nnz_tr, p_emb, p_Rm);

    // P = L @ Db1 + Rm @ Db2
    pad_weights_kernel<<<(2 * SD * SD + 255) / 256, 256>>>(Dense);
    sgemm_kernel<<<gemmGridR, 256>>>(p_Lm, p_Wt, p_P, R_N, 0);
    sgemm_kernel<<<gemmGridR, 256>>>(p_Rm, p_Wt + SD * SD, p_P, R_N, 1);

    zero_out_kernel<<<1, 1>>>(out);

    // h = emb + relu(A1 + er_gather + Bias) -> A2, splits -> Ch/Cl (fused)
    h_er_kernel<<<GW, 256>>>(p_er_ptr, p_er_perm, er_cols, er_vals, Bias);

    // layer 1: t1 = h@W1 -> A3; gcn1 gather -> A5 (2 col passes); gate GEMM fuses highway -> A6
    mgemm_kernel<<<mmGrid, 256, MM_SMEM>>>(p_Ch, p_Cl, p_WTh + 1 * WOFF, p_WTl + 1 * WOFF, p_A3, E_N, 0, 0, 0, 0, 0, 0);
    gspmm_kernel<<<GW, 256>>>(p_adj_ptr, p_adj_perm, adj_cols, adj_vals, p_A3, p_A5, E_N, 0, 40);
    gspmm_kernel<<<GW, 256>>>(p_adj_ptr, p_adj_perm, adj_cols, adj_vals, p_A3, p_A5, E_N, 160, 35);
    mgemm_kernel<<<mmGrid, 256, MM_SMEM>>>(p_Ch, p_Cl, p_WTh + 3 * WOFF, p_WTl + 3 * WOFF, p_A6, E_N, 4, p_A2, p_A5, bg, p_Bh, p_Bl);

    // layer 2: t2 = hg1@W2 -> A3; gcn2 gather -> A1 (2 col passes); gate GEMM fuses highway -> node (A2)
    mgemm_kernel<<<mmGrid, 256, MM_SMEM>>>(p_Bh, p_Bl, p_WTh + 2 * WOFF, p_WTl + 2 * WOFF, p_A3, E_N, 0, 0, 0, 0, 0, 0);
    gspmm_kernel<<<GW, 256>>>(p_adj_ptr, p_adj_perm, adj_cols, adj_vals, p_A3, p_A1, E_N, 0, 40);
    gspmm_kernel<<<GW, 256>>>(p_adj_ptr, p_adj_perm, adj_cols, adj_vals, p_A3, p_A1, E_N, 160, 35);
    mgemm_kernel<<<mmGrid, 256, MM_SMEM>>>(p_Bh, p_Bl, p_WTh + 3 * WOFF, p_WTl + 3 * WOFF, p_A2, E_N, 3, p_A6, p_A1, bg, 0, 0);

    // fused loss
    loss_kernel<<<T_N, 256>>>(pos_left, pos_right, neg_right, neg_left, mask, p_A2, out);
    (void)n_in; (void)out_size;
}

// round 16
// speedup vs baseline: 1.0576x; 1.0576x over previous
#include <cuda_runtime.h>
#include <cuda_bf16.h>
#include <math.h>
#include <stdint.h>

#define E_N 100000
#define D_N 300
#define R_N 1000
#define T_N 10000
#define K_N 25
#define SD  320
#define D4  75
#define SD4 80
#define GAMMA_F 1.0f
#define WOFF (320*320)
#define NNZ_ADJ 600000
#define NNZ_ER  300000

// ---------------- scratch (device globals: allocation-free) ----------------
__device__ float g_emb[(size_t)E_N * SD];
__device__ float g_A1 [(size_t)E_N * SD];
__device__ float g_A2 [(size_t)E_N * SD];
__device__ float g_A3 [(size_t)E_N * SD];
__device__ float g_A5 [(size_t)E_N * SD];
__device__ float g_A6 [(size_t)E_N * SD];
__device__ float g_Lm [R_N * SD];
__device__ float g_Rm [R_N * SD];
__device__ float g_P  [R_N * SD];
__device__ float g_Wt [2 * SD * SD];
__device__ __nv_bfloat16 g_Bh[(size_t)E_N * SD];  // split pair A (emb, then hg1)
__device__ __nv_bfloat16 g_Bl[(size_t)E_N * SD];
__device__ __nv_bfloat16 g_Ch[(size_t)E_N * SD];  // split pair B (h)
__device__ __nv_bfloat16 g_Cl[(size_t)E_N * SD];
__device__ __nv_bfloat16 g_WTh[4 * WOFF];         // transposed weights hi: 0:Dt 1:W1 2:W2 3:KG
__device__ __nv_bfloat16 g_WTl[4 * WOFF];
// CSR scratch (cols/vals materialized in CSR order — no perm indirection in gathers)
__device__ int   g_adj_ptr[E_N + 1];
__device__ int   g_adj_cur[E_N];
__device__ int   g_adj_c[NNZ_ADJ];
__device__ float g_adj_v[NNZ_ADJ];
__device__ int   g_er_ptr[E_N + 1];
__device__ int   g_er_cur[E_N];
__device__ int   g_er_c[NNZ_ER];
__device__ float g_er_v[NNZ_ER];
__device__ int   g_bsum[256];

// ---------------- helpers ----------------
__device__ __forceinline__ uint32_t smem_to_u32(const void* p) {
    uint32_t a;
    asm("{ .reg .u64 t; cvta.to.shared.u64 t, %1; cvt.u32.u64 %0, t; }" : "=r"(a) : "l"(p));
    return a;
}
__device__ __forceinline__ float warp_sum(float v) {
#pragma unroll
    for (int o = 16; o > 0; o >>= 1) v += __shfl_xor_sync(0xffffffffu, v, o);
    return v;
}
__device__ __forceinline__ int warp_sum_i(int v) {
#pragma unroll
    for (int o = 16; o > 0; o >>= 1) v += __shfl_xor_sync(0xffffffffu, v, o);
    return v;
}
__device__ __forceinline__ unsigned long long bcast2(float x) {
    unsigned long long r;
    asm("mov.b64 %0, {%1, %1};" : "=l"(r) : "f"(x));
    return r;
}
__device__ __forceinline__ float2 unpack2(unsigned long long v) {
    float2 f;
    asm("mov.b64 {%0, %1}, %2;" : "=f"(f.x), "=f"(f.y) : "l"(v));
    return f;
}
__device__ __forceinline__ void ffma2(unsigned long long& d, unsigned long long a, unsigned long long b) {
    asm("fma.rn.f32x2 %0, %1, %2, %0;" : "+l"(d) : "l"(a), "l"(b));
}
__device__ __forceinline__ void red_add_v4(float* p, float a, float b, float c, float d) {
    asm volatile("red.global.add.v4.f32 [%0], {%1, %2, %3, %4};"
                 :: "l"(p), "f"(a), "f"(b), "f"(c), "f"(d) : "memory");
}
__device__ __forceinline__ void cp16(uint32_t dst, const void* src, int src_bytes) {
    asm volatile("cp.async.cg.shared.global [%0], [%1], 16, %2;"
                 :: "r"(dst), "l"(src), "r"(src_bytes) : "memory");
}
#define CP_COMMIT() asm volatile("cp.async.commit_group;" ::: "memory")
template <int N>
__device__ __forceinline__ void cp_wait() {
    asm volatile("cp.async.wait_group %0;" :: "n"(N) : "memory");
}
__device__ __forceinline__ void ldsm4(uint32_t* r, uint32_t addr) {
    asm volatile("ldmatrix.sync.aligned.m8n8.x4.shared.b16 {%0,%1,%2,%3}, [%4];"
                 : "=r"(r[0]), "=r"(r[1]), "=r"(r[2]), "=r"(r[3]) : "r"(addr));
}
__device__ __forceinline__ void mma16816(float* d, const uint32_t* a, uint32_t b0, uint32_t b1) {
    asm volatile("mma.sync.aligned.m16n8k16.row.col.f32.bf16.bf16.f32 "
                 "{%0,%1,%2,%3}, {%4,%5,%6,%7}, {%8,%9}, {%0,%1,%2,%3};"
                 : "+f"(d[0]), "+f"(d[1]), "+f"(d[2]), "+f"(d[3])
                 : "r"(a[0]), "r"(a[1]), "r"(a[2]), "r"(a[3]), "r"(b0), "r"(b1));
}
__device__ __forceinline__ void split2(float v, __nv_bfloat16& h, __nv_bfloat16& l) {
    h = __float2bfloat16_rn(v);
    l = __float2bfloat16_rn(v - __bfloat162float(h));
}

// ---------------- CSR build kernels ----------------
__global__ void zcnt_kernel(int* cnt, int n) {
    int i = blockIdx.x * blockDim.x + threadIdx.x;
    if (i < n) cnt[i] = 0;
}
__global__ void hist_kernel(const int* __restrict__ rows, int nnz, int* cnt) {
    int i = blockIdx.x * blockDim.x + threadIdx.x;
    if (i < nnz) atomicAdd(&cnt[rows[i]], 1);
}
__global__ void scan1_kernel(const int* __restrict__ cnt, int n, int* bsum) {
    __shared__ int sh[8];
    int t = threadIdx.x, base = blockIdx.x * 1024 + t * 4;
    int s = 0;
#pragma unroll
    for (int q = 0; q < 4; q++) if (base + q < n) s += cnt[base + q];
    s = warp_sum_i(s);
    if ((t & 31) == 0) sh[t >> 5] = s;
    __syncthreads();
    if (t == 0) {
        int tot = 0;
#pragma unroll
        for (int w = 0; w < 8; w++) tot += sh[w];
        bsum[blockIdx.x] = tot;
    }
}
__global__ void scan2_kernel(int* bsum, int nb) {
    if (threadIdx.x == 0 && blockIdx.x == 0) {
        int run = 0;
        for (int i = 0; i < nb; i++) { int v = bsum[i]; bsum[i] = run; run += v; }
    }
}
__global__ void scan3_kernel(const int* __restrict__ cnt, const int* __restrict__ bsum,
                             int n, int* rowptr, int* cursor) {
    __shared__ int ts[256];
    int t = threadIdx.x, b = blockIdx.x;
    int base = b * 1024 + t * 4;
    int v[4], s = 0;
#pragma unroll
    for (int q = 0; q < 4; q++) { v[q] = (base + q < n) ? cnt[base + q] : 0; s += v[q]; }
    ts[t] = s;
    __syncthreads();
#pragma unroll
    for (int off = 1; off < 256; off <<= 1) {
        int x = (t >= off) ? ts[t - off] : 0;
        __syncthreads();
        ts[t] += x;
        __syncthreads();
    }
    int pre = bsum[b] + (t ? ts[t - 1] : 0);
#pragma unroll
    for (int q = 0; q < 4; q++) {
        int i = base + q;
        if (i < n) {
            rowptr[i] = pre;
            cursor[i] = pre;
            pre += v[q];
            if (i == n - 1) rowptr[n] = pre;
        }
    }
}
// scatter cols/vals directly into CSR order (no perm array)
__global__ void scatter_kernel(const int* __restrict__ rows, const int* __restrict__ cols,
                               const float* __restrict__ vals, int nnz,
                               int* cursor, int* oc, float* ov) {
    int i = blockIdx.x * blockDim.x + threadIdx.x;
    if (i < nnz) {
        int pos = atomicAdd(&cursor[rows[i]], 1);
        oc[pos] = cols[i];
        ov[pos] = vals[i];
    }
}

// ---------------- small kernels ----------------
__global__ void zero_out_kernel(float* out) { if (threadIdx.x == 0 && blockIdx.x == 0) out[0] = 0.0f; }

__global__ void zero4_kernel(float4* p, int n4) {
    int i = blockIdx.x * blockDim.x + threadIdx.x;
    if (i < n4) p[i] = make_float4(0.f, 0.f, 0.f, 0.f);
}

__global__ void pad_weights_kernel(const float* __restrict__ Dense) {
    int idx = blockIdx.x * blockDim.x + threadIdx.x;
    if (idx >= 2 * SD * SD) return;
    int w = idx / (SD * SD);
    int rem = idx % (SD * SD);
    int r = rem / SD, c = rem % SD;
    float v = 0.f;
    if (r < D_N && c < D_N) v = Dense[(size_t)(D_N * (1 + w) + r) * D_N + c];
    g_Wt[idx] = v;
}

__global__ void wsplit_kernel(const float* __restrict__ Dense, const float* __restrict__ W1,
                              const float* __restrict__ W2, const float* __restrict__ KG) {
    int idx = blockIdx.x * blockDim.x + threadIdx.x;
    if (idx >= 4 * WOFF) return;
    int w = idx / WOFF;
    int rem = idx % WOFF;
    int n = rem / 320, k = rem % 320;
    float v = 0.f;
    if (n < D_N && k < D_N) {
        const float* src = (w == 0) ? Dense : (w == 1) ? W1 : (w == 2) ? W2 : KG;
        v = src[(size_t)k * D_N + n];
    }
    __nv_bfloat16 hi, lo;
    split2(v, hi, lo);
    g_WTh[idx] = hi;
    g_WTl[idx] = lo;
}

// normalize + emb splits (to Bh/Bl). Warp per row.
__global__ void normalize_kernel(const float* __restrict__ we) {
    int warp = (blockIdx.x * blockDim.x + threadIdx.x) >> 5;
    int lane = threadIdx.x & 31;
    if (warp >= E_N) return;
    const float4* src = (const float4*)(we + (size_t)warp * D_N);
    float4 v[3];
    float s = 0.f;
#pragma unroll
    for (int it = 0; it < 3; it++) {
        int j = lane + it * 32;
        if (j < D4) {
            float4 x = src[j];
            v[it] = x;
            s += x.x * x.x + x.y * x.y + x.z * x.z + x.w * x.w;
        } else v[it] = make_float4(0.f, 0.f, 0.f, 0.f);
    }
    s = warp_sum(s);
    float inv = 1.0f / sqrtf(s);
    float4* dst = (float4*)(g_emb + (size_t)warp * SD);
    __nv_bfloat162* bh = (__nv_bfloat162*)(g_Bh + (size_t)warp * SD);
    __nv_bfloat162* bl = (__nv_bfloat162*)(g_Bl + (size_t)warp * SD);
#pragma unroll
    for (int it = 0; it < 3; it++) {
        int j = lane + it * 32;
        if (j < SD4) {
            float4 o = make_float4(0.f, 0.f, 0.f, 0.f);
            if (j < D4) o = make_float4(v[it].x * inv, v[it].y * inv, v[it].z * inv, v[it].w * inv);
            dst[j] = o;
            float xs[4] = {o.x, o.y, o.z, o.w};
            __nv_bfloat16 h[4], l[4];
#pragma unroll
            for (int q = 0; q < 4; q++) split2(xs[q], h[q], l[q]);
            __nv_bfloat162 h0, h1, l0, l1;
            h0.x = h[0]; h0.y = h[1]; h1.x = h[2]; h1.y = h[3];
            l0.x = l[0]; l0.y = l[1]; l1.x = l[2]; l1.y = l[3];
            bh[2 * j] = h0; bh[2 * j + 1] = h1;
            bl[2 * j] = l0; bl[2 * j + 1] = l1;
        }
    }
}

// COO SpMM scatter (hr/tr only). Warp per nnz.
__global__ void spmm_kernel(const int* __restrict__ rows, const int* __restrict__ cols,
                            const float* __restrict__ vals, int nnz,
                            const float* __restrict__ X, float* __restrict__ Out) {
    int warp = (blockIdx.x * blockDim.x + threadIdx.x) >> 5;
    int lane = threadIdx.x & 31;
    if (warp >= nnz) return;
    int   r = rows[warp];
    int   c = cols[warp];
    float v = vals[warp];
    const float4* xr = (const float4*)(X + (size_t)c * SD);
    float* orow = Out + (size_t)r * SD;
#pragma unroll
    for (int it = 0; it < 3; it++) {
        int j = lane + it * 32;
        if (j < D4) {
            float4 x = xr[j];
            red_add_v4(orow + j * 4, v * x.x, v * x.y, v * x.z, v * x.w);
        }
    }
}

// CSR gather SpMM (single pass, full width): warp per output row, no atomics.
__global__ void gspmm_kernel(const int* __restrict__ rowptr,
                             const int* __restrict__ cols, const float* __restrict__ vals,
                             const float* __restrict__ X, float* __restrict__ Out, int n_rows) {
    int warp = (blockIdx.x * blockDim.x + threadIdx.x) >> 5;
    int lane = threadIdx.x & 31;
    if (warp >= n_rows) return;
    int s = rowptr[warp], e = rowptr[warp + 1];
    float4 a0 = make_float4(0.f, 0.f, 0.f, 0.f);
    float4 a1 = a0, a2 = a0;
    for (int idx = s; idx < e; idx++) {
        int c = cols[idx];
        float v = vals[idx];
        const float4* xr = (const float4*)(X + (size_t)c * SD);
        float4 x0 = xr[lane], x1 = xr[lane + 32];
        a0.x += v * x0.x; a0.y += v * x0.y; a0.z += v * x0.z; a0.w += v * x0.w;
        a1.x += v * x1.x; a1.y += v * x1.y; a1.z += v * x1.z; a1.w += v * x1.w;
        if (lane < 11) {
            float4 x2 = xr[lane + 64];
            a2.x += v * x2.x; a2.y += v * x2.y; a2.z += v * x2.z; a2.w += v * x2.w;
        }
    }
    float4* o = (float4*)(Out + (size_t)warp * SD);
    o[lane] = a0;
    o[lane + 32] = a1;
    if (lane < 11) o[lane + 64] = a2;
}

// Fused: h = emb + relu(A1 + er_gather(+-P) + Bias); writes h -> A2 and splits -> Ch/Cl.
__global__ void h_er_kernel(const int* __restrict__ rowptr,
                            const int* __restrict__ cols, const float* __restrict__ vals,
                            const float* __restrict__ Bias) {
    int warp = (blockIdx.x * blockDim.x + threadIdx.x) >> 5;
    int lane = threadIdx.x & 31;
    if (warp >= E_N) return;
    const float4* pr = (const float4*)(g_A1 + (size_t)warp * SD);
    float4 a0 = pr[lane], a1 = pr[lane + 32];
    float4 a2 = make_float4(0.f, 0.f, 0.f, 0.f);
    if (lane < 11) a2 = pr[lane + 64];
    int s = rowptr[warp], e = rowptr[warp + 1];
    for (int idx = s; idx < e; idx++) {
        int c = cols[idx];
        float v = vals[idx];
        if (c >= R_N) { c -= R_N; v = -v; }
        const float4* xr = (const float4*)(g_P + (size_t)c * SD);
        float4 x0 = xr[lane], x1 = xr[lane + 32];
        a0.x += v * x0.x; a0.y += v * x0.y; a0.z += v * x0.z; a0.w += v * x0.w;
        a1.x += v * x1.x; a1.y += v * x1.y; a1.z += v * x1.z; a1.w += v * x1.w;
        if (lane < 11) {
            float4 x2 = xr[lane + 64];
            a2.x += v * x2.x; a2.y += v * x2.y; a2.z += v * x2.z; a2.w += v * x2.w;
        }
    }
    const float4* er = (const float4*)(g_emb + (size_t)warp * SD);
    float4* ho = (float4*)(g_A2 + (size_t)warp * SD);
    __nv_bfloat162* ch = (__nv_bfloat162*)(g_Ch + (size_t)warp * SD);
    __nv_bfloat162* cl = (__nv_bfloat162*)(g_Cl + (size_t)warp * SD);
    float4 accs[3] = {a0, a1, a2};
#pragma unroll
    for (int it = 0; it < 3; it++) {
        int j = lane + it * 32;
        if (j >= SD4) continue;
        float4 o = make_float4(0.f, 0.f, 0.f, 0.f);
        if (j < D4) {
            float4 em = er[j];
            float4 a = accs[it];
            int d = j * 4;
            o.x = em.x + fmaxf(a.x + Bias[d + 0], 0.f);
            o.y = em.y + fmaxf(a.y + Bias[d + 1], 0.f);
            o.z = em.z + fmaxf(a.z + Bias[d + 2], 0.f);
            o.w = em.w + fmaxf(a.w + Bias[d + 3], 0.f);
        }
        ho[j] = o;
        float xs[4] = {o.x, o.y, o.z, o.w};
        __nv_bfloat16 h[4], l[4];
#pragma unroll
        for (int q = 0; q < 4; q++) split2(xs[q], h[q], l[q]);
        __nv_bfloat162 h0, h1, l0, l1;
        h0.x = h[0]; h0.y = h[1]; h1.x = h[2]; h1.y = h[3];
        l0.x = l[0]; l0.y = l[1]; l1.x = l[2]; l1.y = l[3];
        ch[2 * j] = h0; ch[2 * j + 1] = h1;
        cl[2 * j] = l0; cl[2 * j + 1] = l1;
    }
}

// ---------------- HMMA GEMM (bf16 split-2): C[M,320] = X @ W ----------------
#define MMN 160
#define MMK 32
#define MMS 40
#define A_TB (128 * MMS * 2)
#define B_TB (MMN * MMS * 2)
#define MM_STAGE (2 * A_TB + 2 * B_TB)
#define MM_SMEM  (2 * MM_STAGE)
#define MM_CH 10

__device__ __forceinline__ void mm_load_stage(uint32_t sb,
                                              const __nv_bfloat16* Xh, const __nv_bfloat16* Xl,
                                              const __nv_bfloat16* Wh, const __nv_bfloat16* Wl,
                                              int bm, int bn, int M, int k0, int tid) {
#pragma unroll
    for (int q = 0; q < 9; q++) {
        int idx = q * 256 + tid;
        if (idx < 1024) {
            int part = idx >> 9;
            int r = (idx & 511) >> 2, c = idx & 3;
            const __nv_bfloat16* src = (part ? Xl : Xh) + (size_t)(bm + r) * 320 + k0 + c * 8;
            int ok = (bm + r < M) ? 16 : 0;
            cp16(sb + part * A_TB + r * (MMS * 2) + c * 16, src, ok);
        } else if (idx < 2304) {
            int t = idx - 1024;
            int part = t >= 640 ? 1 : 0;
            int rr = t - part * 640;
            int r = rr >> 2, c = rr & 3;
            const __nv_bfloat16* src = (part ? Wl : Wh) + (size_t)(bn + r) * 320 + k0 + c * 8;
            cp16(sb + 2 * A_TB + part * B_TB + r * (MMS * 2) + c * 16, src, 16);
        }
    }
    CP_COMMIT();
}

__global__ __launch_bounds__(256, 2) void mgemm_kernel(const __nv_bfloat16* __restrict__ Xh,
                                                       const __nv_bfloat16* __restrict__ Xl,
                                                       const __nv_bfloat16* __restrict__ Wh,
                                                       const __nv_bfloat16* __restrict__ Wl,
                                                       float* __restrict__ C, int M, int mode,
                                                       const float* __restrict__ ep1,
                                                       const float* __restrict__ ep2,
                                                       const float* __restrict__ epv,
                                                       __nv_bfloat16* __restrict__ Oh,
                                                       __nv_bfloat16* __restrict__ Ol) {
    extern __shared__ char sm8[];
    uint32_t smb = smem_to_u32(sm8);
    int tid = threadIdx.x, wid = tid >> 5, lane = tid & 31;
    int bn = blockIdx.x * MMN, bm = blockIdx.y * 128;
    int wm = (wid >> 1) * 32;
    int wn = (wid & 1) * 80;

    float acc[2][10][4];
#pragma unroll
    for (int i = 0; i < 2; i++)
#pragma unroll
        for (int j = 0; j < 10; j++)
#pragma unroll
            for (int q = 0; q < 4; q++) acc[i][j][q] = 0.f;

    int aRow = lane & 15, aKsel = (lane >> 4) * 8;
    int bRow = (lane >> 4) * 8 + (lane & 7), bKsel = ((lane >> 3) & 1) * 8;

    mm_load_stage(smb, Xh, Xl, Wh, Wl, bm, bn, M, 0, tid);

    for (int ch = 0; ch < MM_CH; ch++) {
        uint32_t sb = smb + (ch & 1) * MM_STAGE;
        if (ch + 1 < MM_CH)
            mm_load_stage(smb + ((ch + 1) & 1) * MM_STAGE, Xh, Xl, Wh, Wl, bm, bn, M, (ch + 1) * MMK, tid);
        if (ch + 1 < MM_CH) cp_wait<1>(); else cp_wait<0>();
        __syncthreads();
#pragma unroll
        for (int ks = 0; ks < 2; ks++) {
            // K = 304 suffices: k >= 304 is provably zero in both operands
            if (ks == 1 && ch == MM_CH - 1) continue;
            int k0 = ks * 16;
            uint32_t ah[2][4], al[2][4];
#pragma unroll
            for (int i = 0; i < 2; i++) {
                uint32_t ad = sb + ((wm + i * 16 + aRow) * MMS + k0 + aKsel) * 2;
                ldsm4(ah[i], ad);
                ldsm4(al[i], ad + A_TB);
            }
#pragma unroll
            for (int j = 0; j < 5; j++) {
                uint32_t bh[4], bl[4];
                uint32_t bd = sb + 2 * A_TB + ((wn + j * 16 + bRow) * MMS + k0 + bKsel) * 2;
                ldsm4(bh, bd);
                ldsm4(bl, bd + B_TB);
#pragma unroll
                for (int i = 0; i < 2; i++)
#pragma unroll
                    for (int t = 0; t < 2; t++) {
                        float* a4 = acc[i][j * 2 + t];
                        mma16816(a4, ah[i], bh[t * 2], bh[t * 2 + 1]);
                        mma16816(a4, ah[i], bl[t * 2], bl[t * 2 + 1]);
                        mma16816(a4, al[i], bh[t * 2], bh[t * 2 + 1]);
                    }
            }
        }
        __syncthreads();
    }

#pragma unroll
    for (int i = 0; i < 2; i++)
#pragma unroll
        for (int jj = 0; jj < 10; jj++) {
            int col = bn + wn + jj * 8 + (lane & 3) * 2;
#pragma unroll
            for (int half = 0; half < 2; half++) {
                int row = bm + wm + i * 16 + (lane >> 2) + half * 8;
                if (row >= M) continue;
                float v0 = acc[i][jj][half * 2], v1 = acc[i][jj][half * 2 + 1];
                float* crow = C + (size_t)row * SD + col;
                if (mode == 0) {
                    *(float2*)crow = make_float2(v0, v1);
                } else {
                    const float* l1 = ep1 + (size_t)row * SD + col;
                    const float* gc = ep2 + (size_t)row * SD + col;
                    float2 a = *(const float2*)l1;
                    float2 g = *(const float2*)gc;
                    float o0 = 0.f, o1 = 0.f;
                    if (col < D_N) {
                        float tg = 1.0f / (1.0f + expf(-(v0 + epv[col])));
                        o0 = tg * fmaxf(g.x, 0.f) + (1.0f - tg) * a.x;
                    }
                    if (col + 1 < D_N) {
                        float tg = 1.0f / (1.0f + expf(-(v1 + epv[col + 1])));
                        o1 = tg * fmaxf(g.y, 0.f) + (1.0f - tg) * a.y;
                    }
                    *(float2*)crow = make_float2(o0, o1);
                    if (mode == 4) {
                        __nv_bfloat16 h0, h1, l0, l1b;
                        split2(o0, h0, l0);
                        split2(o1, h1, l1b);
                        __nv_bfloat162 hh, ll;
                        hh.x = h0; hh.y = h1;
                        ll.x = l0; ll.y = l1b;
                        *(__nv_bfloat162*)(Oh + (size_t)row * SD + col) = hh;
                        *(__nv_bfloat162*)(Ol + (size_t)row * SD + col) = ll;
                    }
                }
            }
        }
}

// ---------------- FFMA2 SGEMM (small R_N GEMMs) ----------------
#define BM 256
#define BN 64
#define BK 16
#define KTILES 19
__global__ __launch_bounds__(256, 2) void sgemm_kernel(const float* __restrict__ A,
                                                       const float* __restrict__ B,
                                                       float* __restrict__ C,
                                                       int M, int accumulate) {
    __shared__ float As[2][BK][BM];
    __shared__ float Bs[2][BK][BN];
    int bm = blockIdx.y * BM;
    int bn = blockIdx.x * BN;
    int tid = threadIdx.x;
    int tx = tid & 7;
    int ty = tid >> 3;
    int arow = bm + tid;
    bool avalid = arow < M;
    const float* Aptr = A + (size_t)arow * SD;
    int brow  = tid >> 4;
    int bcol4 = tid & 15;
    const float* Bptr = B + (size_t)brow * SD + bn + bcol4 * 4;

    unsigned long long acc[8][4];
#pragma unroll
    for (int i = 0; i < 8; i++)
#pragma unroll
        for (int j = 0; j < 4; j++) acc[i][j] = 0ull;

    float4 ra[4], rb;
#pragma unroll
    for (int c = 0; c < 4; c++)
        ra[c] = avalid ? *(const float4*)(Aptr + c * 4) : make_float4(0.f, 0.f, 0.f, 0.f);
    rb = *(const float4*)(Bptr);
#pragma unroll
    for (int c = 0; c < 4; c++) {
        As[0][c * 4 + 0][tid] = ra[c].x;
        As[0][c * 4 + 1][tid] = ra[c].y;
        As[0][c * 4 + 2][tid] = ra[c].z;
        As[0][c * 4 + 3][tid] = ra[c].w;
    }
    *(float4*)(&Bs[0][brow][bcol4 * 4]) = rb;
    __syncthreads();

    for (int t = 0; t < KTILES; t++) {
        int cur = t & 1, nxt = cur ^ 1;
        if (t + 1 < KTILES) {
            int k0 = (t + 1) * BK;
#pragma unroll
            for (int c = 0; c < 4; c++)
                ra[c] = avalid ? *(const float4*)(Aptr + k0 + c * 4) : make_float4(0.f, 0.f, 0.f, 0.f);
            rb = *(const float4*)(Bptr + (size_t)k0 * SD);
        }
#pragma unroll
        for (int k = 0; k < BK; k++) {
            ulonglong2 bb0 = *(const ulonglong2*)(&Bs[cur][k][tx * 8]);
            ulonglong2 bb1 = *(const ulonglong2*)(&Bs[cur][k][tx * 8 + 4]);
            unsigned long long b2[4] = {bb0.x, bb0.y, bb1.x, bb1.y};
            float4 a0 = *(const float4*)(&As[cur][k][ty * 8]);
            float4 a1 = *(const float4*)(&As[cur][k][ty * 8 + 4]);
            unsigned long long a2[8];
            a2[0] = bcast2(a0.x); a2[1] = bcast2(a0.y); a2[2] = bcast2(a0.z); a2[3] = bcast2(a0.w);
            a2[4] = bcast2(a1.x); a2[5] = bcast2(a1.y); a2[6] = bcast2(a1.z); a2[7] = bcast2(a1.w);
#pragma unroll
            for (int i = 0; i < 8; i++)
#pragma unroll
                for (int j = 0; j < 4; j++)
                    ffma2(acc[i][j], a2[i], b2[j]);
        }
        if (t + 1 < KTILES) {
#pragma unroll
            for (int c = 0; c < 4; c++) {
                As[nxt][c * 4 + 0][tid] = ra[c].x;
                As[nxt][c * 4 + 1][tid] = ra[c].y;
                As[nxt][c * 4 + 2][tid] = ra[c].z;
                As[nxt][c * 4 + 3][tid] = ra[c].w;
            }
            *(float4*)(&Bs[nxt][brow][bcol4 * 4]) = rb;
        }
        __syncthreads();
    }

    int gcol = bn + tx * 8;
#pragma unroll
    for (int i = 0; i < 8; i++) {
        int grow = bm + ty * 8 + i;
        if (grow >= M) continue;
        float2 u0 = unpack2(acc[i][0]);
        float2 u1 = unpack2(acc[i][1]);
        float2 u2 = unpack2(acc[i][2]);
        float2 u3 = unpack2(acc[i][3]);
        float* crow = C + (size_t)grow * SD + gcol;
        if (accumulate) {
            float4 c0 = *(float4*)crow;
            float4 c1 = *(float4*)(crow + 4);
            *(float4*)crow       = make_float4(c0.x + u0.x, c0.y + u0.y, c0.z + u1.x, c0.w + u1.y);
            *(float4*)(crow + 4) = make_float4(c1.x + u2.x, c1.y + u2.y, c1.z + u3.x, c1.w + u3.y);
        } else {
            *(float4*)crow       = make_float4(u0.x, u0.y, u1.x, u1.y);
            *(float4*)(crow + 4) = make_float4(u2.x, u2.y, u3.x, u3.y);
        }
    }
}

// Fused hinge loss: one block per pair t.
__global__ __launch_bounds__(256) void loss_kernel(const int* __restrict__ pl,
                                                   const int* __restrict__ pr,
                                                   const int* __restrict__ nr,
                                                   const int* __restrict__ nl,
                                                   const float* __restrict__ mask,
                                                   const float* __restrict__ node,
                                                   float* __restrict__ out) {
    __shared__ float4 sl[D4], sr[D4];
    __shared__ float wpart[8];
    __shared__ float s_dm;
    int t    = blockIdx.x;
    int tid  = threadIdx.x;
    int lane = tid & 31;
    int wid  = tid >> 5;

    const float4* xl = (const float4*)(node + (size_t)pl[t] * SD);
    const float4* xr = (const float4*)(node + (size_t)pr[t] * SD);
    float d = 0.f;
    if (tid < D4) {
        float4 a = xl[tid], b = xr[tid];
        sl[tid] = a; sr[tid] = b;
        d = fabsf(a.x - b.x) + fabsf(a.y - b.y) + fabsf(a.z - b.z) + fabsf(a.w - b.w);
    }
    d = warp_sum(d);
    if (lane == 0) wpart[wid] = d;
    __syncthreads();
    if (tid == 0) s_dm = wpart[0] + wpart[1] + wpart[2] + GAMMA_F;
    __syncthreads();
    float dm = s_dm;

    float hsum = 0.f;
    for (int k = wid; k < K_N; k += 8) {
        int i = t * K_N + k;
        const float4* xR = (const float4*)(node + (size_t)nr[i] * SD);
        const float4* xL = (const float4*)(node + (size_t)nl[i] * SD);
        float s1 = 0.f, s2 = 0.f;
#pragma unroll
        for (int it = 0; it < 3; it++) {
            int j = lane + it * 32;
            if (j < D4) {
                float4 a = sl[j], b = sr[j], cr = xR[j], cl = xL[j];
                s1 += fabsf(a.x - cr.x) + fabsf(a.y - cr.y) + fabsf(a.z - cr.z) + fabsf(a.w - cr.w);
                s2 += fabsf(cl.x - b.x) + fabsf(cl.y - b.y) + fabsf(cl.z - b.z) + fabsf(cl.w - b.w);
            }
        }
        s1 = warp_sum(s1);
        s2 = warp_sum(s2);
        if (lane == 0) hsum += (fmaxf(dm - s1, 0.f) + fmaxf(dm - s2, 0.f)) * mask[i];
    }
    if (lane == 0) wpart[wid] = hsum;
    __syncthreads();
    if (tid == 0) {
        float tot = 0.f;
#pragma unroll
        for (int w = 0; w < 8; w++) tot += wpart[w];
        atomicAdd(out, tot * 0.5f);
    }
}

// ---------------- host ----------------
extern "C" void kernel_launch(void* const* d_in, const int* in_sizes, int n_in,
                              void* d_out, int out_size) {
    const float* we    = (const float*)d_in[0];
    const float* kgw   = (const float*)d_in[1];
    const float* bg    = (const float*)d_in[2];
    const float* W1    = (const float*)d_in[3];
    const float* W2    = (const float*)d_in[4];
    const float* Dense = (const float*)d_in[5];
    const float* Bias  = (const float*)d_in[6];
    const int*   hr_rows = (const int*)d_in[7];
    const int*   hr_cols = (const int*)d_in[8];
    const float* hr_vals = (const float*)d_in[9];
    const int*   tr_rows = (const int*)d_in[10];
    const int*   tr_cols = (const int*)d_in[11];
    const float* tr_vals = (const float*)d_in[12];
    const int*   er_rows = (const int*)d_in[13];
    const int*   er_cols = (const int*)d_in[14];
    const float* er_vals = (const float*)d_in[15];
    const int*   adj_rows = (const int*)d_in[16];
    const int*   adj_cols = (const int*)d_in[17];
    const float* adj_vals = (const float*)d_in[18];
    const int*   pos_left  = (const int*)d_in[19];
    const int*   pos_right = (const int*)d_in[20];
    const int*   neg_right = (const int*)d_in[21];
    const int*   neg_left  = (const int*)d_in[22];
    const float* mask      = (const float*)d_in[23];
    float* out = (float*)d_out;

    int nnz_hr  = in_sizes[7];
    int nnz_tr  = in_sizes[10];
    int nnz_er  = in_sizes[13];
    int nnz_adj = in_sizes[16];

    float *p_emb, *p_A1, *p_A2, *p_A3, *p_A5, *p_A6, *p_Lm, *p_Rm, *p_P, *p_Wt;
    __nv_bfloat16 *p_Bh, *p_Bl, *p_Ch, *p_Cl, *p_WTh, *p_WTl;
    int *p_adj_ptr, *p_adj_cur, *p_adj_c, *p_er_ptr, *p_er_cur, *p_er_c, *p_bsum;
    float *p_adj_v, *p_er_v;
    cudaGetSymbolAddress((void**)&p_emb, g_emb);
    cudaGetSymbolAddress((void**)&p_A1,  g_A1);
    cudaGetSymbolAddress((void**)&p_A2,  g_A2);
    cudaGetSymbolAddress((void**)&p_A3,  g_A3);
    cudaGetSymbolAddress((void**)&p_A5,  g_A5);
    cudaGetSymbolAddress((void**)&p_A6,  g_A6);
    cudaGetSymbolAddress((void**)&p_Lm,  g_Lm);
    cudaGetSymbolAddress((void**)&p_Rm,  g_Rm);
    cudaGetSymbolAddress((void**)&p_P,   g_P);
    cudaGetSymbolAddress((void**)&p_Wt,  g_Wt);
    cudaGetSymbolAddress((void**)&p_Bh,  g_Bh);
    cudaGetSymbolAddress((void**)&p_Bl,  g_Bl);
    cudaGetSymbolAddress((void**)&p_Ch,  g_Ch);
    cudaGetSymbolAddress((void**)&p_Cl,  g_Cl);
    cudaGetSymbolAddress((void**)&p_WTh, g_WTh);
    cudaGetSymbolAddress((void**)&p_WTl, g_WTl);
    cudaGetSymbolAddress((void**)&p_adj_ptr, g_adj_ptr);
    cudaGetSymbolAddress((void**)&p_adj_cur, g_adj_cur);
    cudaGetSymbolAddress((void**)&p_adj_c,   g_adj_c);
    cudaGetSymbolAddress((void**)&p_adj_v,   g_adj_v);
    cudaGetSymbolAddress((void**)&p_er_ptr,  g_er_ptr);
    cudaGetSymbolAddress((void**)&p_er_cur,  g_er_cur);
    cudaGetSymbolAddress((void**)&p_er_c,    g_er_c);
    cudaGetSymbolAddress((void**)&p_er_v,    g_er_v);
    cudaGetSymbolAddress((void**)&p_bsum,    g_bsum);

    cudaFuncSetAttribute(mgemm_kernel, cudaFuncAttributeMaxDynamicSharedMemorySize, MM_SMEM);

    dim3 mmGrid(SD / MMN, (E_N + 127) / 128);       // (2, 782)
    dim3 gemmGridR(SD / BN, (R_N + BM - 1) / BM);
    const int NB_E = (E_N + 1023) / 1024;           // 98
    const int GW = (E_N * 32 + 255) / 256;          // warp-per-row grids

    // 1-3, then launch #4 = first HMMA GEMM (profiled)
    wsplit_kernel<<<(4 * WOFF + 255) / 256, 256>>>(Dense, W1, W2, kgw);
    normalize_kernel<<<GW, 256>>>(we);
    zero4_kernel<<<(R_N * SD / 4 + 255) / 256, 256>>>((float4*)p_Lm, R_N * SD / 4);
    mgemm_kernel<<<mmGrid, 256, MM_SMEM>>>(p_Bh, p_Bl, p_WTh, p_WTl, p_A1, E_N, 0, 0, 0, 0, 0, 0);

    // ---- CSR build: adj ----
    zcnt_kernel<<<(E_N + 255) / 256, 256>>>(p_adj_cur, E_N);
    hist_kernel<<<(nnz_adj + 255) / 256, 256>>>(adj_rows, nnz_adj, p_adj_cur);
    scan1_kernel<<<NB_E, 256>>>(p_adj_cur, E_N, p_bsum);
    scan2_kernel<<<1, 32>>>(p_bsum, NB_E);
    scan3_kernel<<<NB_E, 256>>>(p_adj_cur, p_bsum, E_N, p_adj_ptr, p_adj_cur);
    scatter_kernel<<<(nnz_adj + 255) / 256, 256>>>(adj_rows, adj_cols, adj_vals, nnz_adj,
                                                   p_adj_cur, p_adj_c, p_adj_v);

    // ---- CSR build: er ----
    zcnt_kernel<<<(E_N + 255) / 256, 256>>>(p_er_cur, E_N);
    hist_kernel<<<(nnz_er + 255) / 256, 256>>>(er_rows, nnz_er, p_er_cur);
    scan1_kernel<<<NB_E, 256>>>(p_er_cur, E_N, p_bsum);
    scan2_kernel<<<1, 32>>>(p_bsum, NB_E);
    scan3_kernel<<<NB_E, 256>>>(p_er_cur, p_bsum, E_N, p_er_ptr, p_er_cur);
    scatter_kernel<<<(nnz_er + 255) / 256, 256>>>(er_rows, er_cols, er_vals, nnz_er,
                                                  p_er_cur, p_er_c, p_er_v);

    // relation aggregation (scatter; small outputs)
    zero4_kernel<<<(R_N * SD / 4 + 255) / 256, 256>>>((float4*)p_Rm, R_N * SD / 4);
    spmm_kernel<<<(nnz_hr + 7) / 8, 256>>>(hr_rows, hr_cols, hr_vals, nnz_hr, p_emb, p_Lm);
    spmm_kernel<<<(nnz_tr + 7) / 8, 256>>>(tr_rows, tr_cols, tr_vals, nnz_tr, p_emb, p_Rm);

    // P = L @ Db1 + Rm @ Db2
    pad_weights_kernel<<<(2 * SD * SD + 255) / 256, 256>>>(Dense);
    sgemm_kernel<<<gemmGridR, 256>>>(p_Lm, p_Wt, p_P, R_N, 0);
    sgemm_kernel<<<gemmGridR, 256>>>(p_Rm, p_Wt + SD * SD, p_P, R_N, 1);

    zero_out_kernel<<<1, 1>>>(out);

    // h = emb + relu(A1 + er_gather + Bias) -> A2, splits -> Ch/Cl (fused)
    h_er_kernel<<<GW, 256>>>(p_er_ptr, p_er_c, p_er_v, Bias);

    // layer 1: t1 = h@W1 -> A3; gcn1 gather -> A5; gate GEMM fuses highway -> A6 (+ splits -> Bh/Bl)
    mgemm_kernel<<<mmGrid, 256, MM_SMEM>>>(p_Ch, p_Cl, p_WTh + 1 * WOFF, p_WTl + 1 * WOFF, p_A3, E_N, 0, 0, 0, 0, 0, 0);
    gspmm_kernel<<<GW, 256>>>(p_adj_ptr, p_adj_c, p_adj_v, p_A3, p_A5, E_N);
    mgemm_kernel<<<mmGrid, 256, MM_SMEM>>>(p_Ch, p_Cl, p_WTh + 3 * WOFF, p_WTl + 3 * WOFF, p_A6, E_N, 4, p_A2, p_A5, bg, p_Bh, p_Bl);

    // layer 2: t2 = hg1@W2 -> A3; gcn2 gather -> A1; gate GEMM fuses highway -> node (A2)
    mgemm_kernel<<<mmGrid, 256, MM_SMEM>>>(p_Bh, p_Bl, p_WTh + 2 * WOFF, p_WTl + 2 * WOFF, p_A3, E_N, 0, 0, 0, 0, 0, 0);
    gspmm_kernel<<<GW, 256>>>(p_adj_ptr, p_adj_c, p_adj_v, p_A3, p_A1, E_N);
    mgemm_kernel<<<mmGrid, 256, MM_SMEM>>>(p_Bh, p_Bl, p_WTh + 3 * WOFF, p_WTl + 3 * WOFF, p_A2, E_N, 3, p_A6, p_A1, bg, 0, 0);

    // fused loss
    loss_kernel<<<T_N, 256>>>(pos_left, pos_right, neg_right, neg_left, mask, p_A2, out);
    (void)n_in; (void)out_size;
}

// round 17
// speedup vs baseline: 1.0780x; 1.0192x over previous
#include <cuda_runtime.h>
#include <cuda_bf16.h>
#include <math.h>
#include <stdint.h>

#define E_N 100000
#define D_N 300
#define R_N 1000
#define T_N 10000
#define K_N 25
#define SD  320
#define D4  75
#define SD4 80
#define GAMMA_F 1.0f
#define WOFF (320*320)
#define NNZ_ADJ 600000
#define NNZ_ER  300000

// ---------------- scratch (device globals: allocation-free) ----------------
__device__ float g_emb[(size_t)E_N * SD];
__device__ float g_A1 [(size_t)E_N * SD];
__device__ float g_A2 [(size_t)E_N * SD];
__device__ float g_A3 [(size_t)E_N * SD];   // reused as bf16 t-GEMM output
__device__ float g_A5 [(size_t)E_N * SD];
__device__ float g_A6 [(size_t)E_N * SD];
__device__ float g_Lm [R_N * SD];
__device__ float g_Rm [R_N * SD];
__device__ float g_P  [R_N * SD];
__device__ float g_Wt [2 * SD * SD];
__device__ __nv_bfloat16 g_Bh[(size_t)E_N * SD];  // split pair A (emb, then hg1)
__device__ __nv_bfloat16 g_Bl[(size_t)E_N * SD];
__device__ __nv_bfloat16 g_Ch[(size_t)E_N * SD];  // split pair B (h); later node bf16
__device__ __nv_bfloat16 g_Cl[(size_t)E_N * SD];
__device__ __nv_bfloat16 g_WTh[4 * WOFF];         // transposed weights hi: 0:Dt 1:W1 2:W2 3:KG
__device__ __nv_bfloat16 g_WTl[4 * WOFF];
// CSR scratch (cols/vals materialized in CSR order)
__device__ int   g_adj_ptr[E_N + 1];
__device__ int   g_adj_cur[E_N];
__device__ int   g_adj_c[NNZ_ADJ];
__device__ float g_adj_v[NNZ_ADJ];
__device__ int   g_er_ptr[E_N + 1];
__device__ int   g_er_cur[E_N];
__device__ int   g_er_c[NNZ_ER];
__device__ float g_er_v[NNZ_ER];
__device__ int   g_bsum[256];

// ---------------- helpers ----------------
__device__ __forceinline__ uint32_t smem_to_u32(const void* p) {
    uint32_t a;
    asm("{ .reg .u64 t; cvta.to.shared.u64 t, %1; cvt.u32.u64 %0, t; }" : "=r"(a) : "l"(p));
    return a;
}
__device__ __forceinline__ float warp_sum(float v) {
#pragma unroll
    for (int o = 16; o > 0; o >>= 1) v += __shfl_xor_sync(0xffffffffu, v, o);
    return v;
}
__device__ __forceinline__ int warp_sum_i(int v) {
#pragma unroll
    for (int o = 16; o > 0; o >>= 1) v += __shfl_xor_sync(0xffffffffu, v, o);
    return v;
}
__device__ __forceinline__ unsigned long long bcast2(float x) {
    unsigned long long r;
    asm("mov.b64 %0, {%1, %1};" : "=l"(r) : "f"(x));
    return r;
}
__device__ __forceinline__ float2 unpack2(unsigned long long v) {
    float2 f;
    asm("mov.b64 {%0, %1}, %2;" : "=f"(f.x), "=f"(f.y) : "l"(v));
    return f;
}
__device__ __forceinline__ void ffma2(unsigned long long& d, unsigned long long a, unsigned long long b) {
    asm("fma.rn.f32x2 %0, %1, %2, %0;" : "+l"(d) : "l"(a), "l"(b));
}
__device__ __forceinline__ void red_add_v4(float* p, float a, float b, float c, float d) {
    asm volatile("red.global.add.v4.f32 [%0], {%1, %2, %3, %4};"
                 :: "l"(p), "f"(a), "f"(b), "f"(c), "f"(d) : "memory");
}
__device__ __forceinline__ void cp16(uint32_t dst, const void* src, int src_bytes) {
    asm volatile("cp.async.cg.shared.global [%0], [%1], 16, %2;"
                 :: "r"(dst), "l"(src), "r"(src_bytes) : "memory");
}
#define CP_COMMIT() asm volatile("cp.async.commit_group;" ::: "memory")
template <int N>
__device__ __forceinline__ void cp_wait() {
    asm volatile("cp.async.wait_group %0;" :: "n"(N) : "memory");
}
__device__ __forceinline__ void ldsm4(uint32_t* r, uint32_t addr) {
    asm volatile("ldmatrix.sync.aligned.m8n8.x4.shared.b16 {%0,%1,%2,%3}, [%4];"
                 : "=r"(r[0]), "=r"(r[1]), "=r"(r[2]), "=r"(r[3]) : "r"(addr));
}
__device__ __forceinline__ void mma16816(float* d, const uint32_t* a, uint32_t b0, uint32_t b1) {
    asm volatile("mma.sync.aligned.m16n8k16.row.col.f32.bf16.bf16.f32 "
                 "{%0,%1,%2,%3}, {%4,%5,%6,%7}, {%8,%9}, {%0,%1,%2,%3};"
                 : "+f"(d[0]), "+f"(d[1]), "+f"(d[2]), "+f"(d[3])
                 : "r"(a[0]), "r"(a[1]), "r"(a[2]), "r"(a[3]), "r"(b0), "r"(b1));
}
__device__ __forceinline__ void split2(float v, __nv_bfloat16& h, __nv_bfloat16& l) {
    h = __float2bfloat16_rn(v);
    l = __float2bfloat16_rn(v - __bfloat162float(h));
}
__device__ __forceinline__ float2 bf2f2(uint32_t u) {
    __nv_bfloat162 b;
    memcpy(&b, &u, 4);
    return __bfloat1622float2(b);
}

// ---------------- CSR build kernels ----------------
__global__ void zcnt_kernel(int* cnt, int n) {
    int i = blockIdx.x * blockDim.x + threadIdx.x;
    if (i < n) cnt[i] = 0;
}
__global__ void hist_kernel(const int* __restrict__ rows, int nnz, int* cnt) {
    int i = blockIdx.x * blockDim.x + threadIdx.x;
    if (i < nnz) atomicAdd(&cnt[rows[i]], 1);
}
__global__ void scan1_kernel(const int* __restrict__ cnt, int n, int* bsum) {
    __shared__ int sh[8];
    int t = threadIdx.x, base = blockIdx.x * 1024 + t * 4;
    int s = 0;
#pragma unroll
    for (int q = 0; q < 4; q++) if (base + q < n) s += cnt[base + q];
    s = warp_sum_i(s);
    if ((t & 31) == 0) sh[t >> 5] = s;
    __syncthreads();
    if (t == 0) {
        int tot = 0;
#pragma unroll
        for (int w = 0; w < 8; w++) tot += sh[w];
        bsum[blockIdx.x] = tot;
    }
}
__global__ void scan2_kernel(int* bsum, int nb) {
    if (threadIdx.x == 0 && blockIdx.x == 0) {
        int run = 0;
        for (int i = 0; i < nb; i++) { int v = bsum[i]; bsum[i] = run; run += v; }
    }
}
__global__ void scan3_kernel(const int* __restrict__ cnt, const int* __restrict__ bsum,
                             int n, int* rowptr, int* cursor) {
    __shared__ int ts[256];
    int t = threadIdx.x, b = blockIdx.x;
    int base = b * 1024 + t * 4;
    int v[4], s = 0;
#pragma unroll
    for (int q = 0; q < 4; q++) { v[q] = (base + q < n) ? cnt[base + q] : 0; s += v[q]; }
    ts[t] = s;
    __syncthreads();
#pragma unroll
    for (int off = 1; off < 256; off <<= 1) {
        int x = (t >= off) ? ts[t - off] : 0;
        __syncthreads();
        ts[t] += x;
        __syncthreads();
    }
    int pre = bsum[b] + (t ? ts[t - 1] : 0);
#pragma unroll
    for (int q = 0; q < 4; q++) {
        int i = base + q;
        if (i < n) {
            rowptr[i] = pre;
            cursor[i] = pre;
            pre += v[q];
            if (i == n - 1) rowptr[n] = pre;
        }
    }
}
__global__ void scatter_kernel(const int* __restrict__ rows, const int* __restrict__ cols,
                               const float* __restrict__ vals, int nnz,
                               int* cursor, int* oc, float* ov) {
    int i = blockIdx.x * blockDim.x + threadIdx.x;
    if (i < nnz) {
        int pos = atomicAdd(&cursor[rows[i]], 1);
        oc[pos] = cols[i];
        ov[pos] = vals[i];
    }
}

// ---------------- small kernels ----------------
__global__ void zero_out_kernel(float* out) { if (threadIdx.x == 0 && blockIdx.x == 0) out[0] = 0.0f; }

__global__ void zero4_kernel(float4* p, int n4) {
    int i = blockIdx.x * blockDim.x + threadIdx.x;
    if (i < n4) p[i] = make_float4(0.f, 0.f, 0.f, 0.f);
}

__global__ void pad_weights_kernel(const float* __restrict__ Dense) {
    int idx = blockIdx.x * blockDim.x + threadIdx.x;
    if (idx >= 2 * SD * SD) return;
    int w = idx / (SD * SD);
    int rem = idx % (SD * SD);
    int r = rem / SD, c = rem % SD;
    float v = 0.f;
    if (r < D_N && c < D_N) v = Dense[(size_t)(D_N * (1 + w) + r) * D_N + c];
    g_Wt[idx] = v;
}

__global__ void wsplit_kernel(const float* __restrict__ Dense, const float* __restrict__ W1,
                              const float* __restrict__ W2, const float* __restrict__ KG) {
    int idx = blockIdx.x * blockDim.x + threadIdx.x;
    if (idx >= 4 * WOFF) return;
    int w = idx / WOFF;
    int rem = idx % WOFF;
    int n = rem / 320, k = rem % 320;
    float v = 0.f;
    if (n < D_N && k < D_N) {
        const float* src = (w == 0) ? Dense : (w == 1) ? W1 : (w == 2) ? W2 : KG;
        v = src[(size_t)k * D_N + n];
    }
    __nv_bfloat16 hi, lo;
    split2(v, hi, lo);
    g_WTh[idx] = hi;
    g_WTl[idx] = lo;
}

// normalize + emb splits (to Bh/Bl). Warp per row.
__global__ void normalize_kernel(const float* __restrict__ we) {
    int warp = (blockIdx.x * blockDim.x + threadIdx.x) >> 5;
    int lane = threadIdx.x & 31;
    if (warp >= E_N) return;
    const float4* src = (const float4*)(we + (size_t)warp * D_N);
    float4 v[3];
    float s = 0.f;
#pragma unroll
    for (int it = 0; it < 3; it++) {
        int j = lane + it * 32;
        if (j < D4) {
            float4 x = src[j];
            v[it] = x;
            s += x.x * x.x + x.y * x.y + x.z * x.z + x.w * x.w;
        } else v[it] = make_float4(0.f, 0.f, 0.f, 0.f);
    }
    s = warp_sum(s);
    float inv = 1.0f / sqrtf(s);
    float4* dst = (float4*)(g_emb + (size_t)warp * SD);
    __nv_bfloat162* bh = (__nv_bfloat162*)(g_Bh + (size_t)warp * SD);
    __nv_bfloat162* bl = (__nv_bfloat162*)(g_Bl + (size_t)warp * SD);
#pragma unroll
    for (int it = 0; it < 3; it++) {
        int j = lane + it * 32;
        if (j < SD4) {
            float4 o = make_float4(0.f, 0.f, 0.f, 0.f);
            if (j < D4) o = make_float4(v[it].x * inv, v[it].y * inv, v[it].z * inv, v[it].w * inv);
            dst[j] = o;
            float xs[4] = {o.x, o.y, o.z, o.w};
            __nv_bfloat16 h[4], l[4];
#pragma unroll
            for (int q = 0; q < 4; q++) split2(xs[q], h[q], l[q]);
            __nv_bfloat162 h0, h1, l0, l1;
            h0.x = h[0]; h0.y = h[1]; h1.x = h[2]; h1.y = h[3];
            l0.x = l[0]; l0.y = l[1]; l1.x = l[2]; l1.y = l[3];
            bh[2 * j] = h0; bh[2 * j + 1] = h1;
            bl[2 * j] = l0; bl[2 * j + 1] = l1;
        }
    }
}

// COO SpMM scatter (hr/tr only). Warp per nnz.
__global__ void spmm_kernel(const int* __restrict__ rows, const int* __restrict__ cols,
                            const float* __restrict__ vals, int nnz,
                            const float* __restrict__ X, float* __restrict__ Out) {
    int warp = (blockIdx.x * blockDim.x + threadIdx.x) >> 5;
    int lane = threadIdx.x & 31;
    if (warp >= nnz) return;
    int   r = rows[warp];
    int   c = cols[warp];
    float v = vals[warp];
    const float4* xr = (const float4*)(X + (size_t)c * SD);
    float* orow = Out + (size_t)r * SD;
#pragma unroll
    for (int it = 0; it < 3; it++) {
        int j = lane + it * 32;
        if (j < D4) {
            float4 x = xr[j];
            red_add_v4(orow + j * 4, v * x.x, v * x.y, v * x.z, v * x.w);
        }
    }
}

// CSR gather SpMM over bf16 source rows: warp per output row, fp32 accumulate, no atomics.
__global__ void gspmm_kernel(const int* __restrict__ rowptr,
                             const int* __restrict__ cols, const float* __restrict__ vals,
                             const __nv_bfloat16* __restrict__ X, float* __restrict__ Out,
                             int n_rows) {
    int warp = (blockIdx.x * blockDim.x + threadIdx.x) >> 5;
    int lane = threadIdx.x & 31;
    if (warp >= n_rows) return;
    int s = rowptr[warp], e = rowptr[warp + 1];
    float4 a0 = make_float4(0.f, 0.f, 0.f, 0.f);
    float4 a1 = a0, a2 = a0;
    for (int idx = s; idx < e; idx++) {
        int c = cols[idx];
        float v = vals[idx];
        const uint2* xr = (const uint2*)(X + (size_t)c * SD);
        uint2 u0 = xr[lane], u1 = xr[lane + 32];
        float2 p0 = bf2f2(u0.x), p1 = bf2f2(u0.y);
        a0.x += v * p0.x; a0.y += v * p0.y; a0.z += v * p1.x; a0.w += v * p1.y;
        float2 q0 = bf2f2(u1.x), q1 = bf2f2(u1.y);
        a1.x += v * q0.x; a1.y += v * q0.y; a1.z += v * q1.x; a1.w += v * q1.y;
        if (lane < 11) {
            uint2 u2 = xr[lane + 64];
            float2 r0 = bf2f2(u2.x), r1 = bf2f2(u2.y);
            a2.x += v * r0.x; a2.y += v * r0.y; a2.z += v * r1.x; a2.w += v * r1.y;
        }
    }
    float4* o = (float4*)(Out + (size_t)warp * SD);
    o[lane] = a0;
    o[lane + 32] = a1;
    if (lane < 11) o[lane + 64] = a2;
}

// Fused: h = emb + relu(A1 + er_gather(+-P) + Bias); writes h -> A2 and splits -> Ch/Cl.
__global__ void h_er_kernel(const int* __restrict__ rowptr,
                            const int* __restrict__ cols, const float* __restrict__ vals,
                            const float* __restrict__ Bias) {
    int warp = (blockIdx.x * blockDim.x + threadIdx.x) >> 5;
    int lane = threadIdx.x & 31;
    if (warp >= E_N) return;
    const float4* pr = (const float4*)(g_A1 + (size_t)warp * SD);
    float4 a0 = pr[lane], a1 = pr[lane + 32];
    float4 a2 = make_float4(0.f, 0.f, 0.f, 0.f);
    if (lane < 11) a2 = pr[lane + 64];
    int s = rowptr[warp], e = rowptr[warp + 1];
    for (int idx = s; idx < e; idx++) {
        int c = cols[idx];
        float v = vals[idx];
        if (c >= R_N) { c -= R_N; v = -v; }
        const float4* xr = (const float4*)(g_P + (size_t)c * SD);
        float4 x0 = xr[lane], x1 = xr[lane + 32];
        a0.x += v * x0.x; a0.y += v * x0.y; a0.z += v * x0.z; a0.w += v * x0.w;
        a1.x += v * x1.x; a1.y += v * x1.y; a1.z += v * x1.z; a1.w += v * x1.w;
        if (lane < 11) {
            float4 x2 = xr[lane + 64];
            a2.x += v * x2.x; a2.y += v * x2.y; a2.z += v * x2.z; a2.w += v * x2.w;
        }
    }
    const float4* er = (const float4*)(g_emb + (size_t)warp * SD);
    float4* ho = (float4*)(g_A2 + (size_t)warp * SD);
    __nv_bfloat162* ch = (__nv_bfloat162*)(g_Ch + (size_t)warp * SD);
    __nv_bfloat162* cl = (__nv_bfloat162*)(g_Cl + (size_t)warp * SD);
    float4 accs[3] = {a0, a1, a2};
#pragma unroll
    for (int it = 0; it < 3; it++) {
        int j = lane + it * 32;
        if (j >= SD4) continue;
        float4 o = make_float4(0.f, 0.f, 0.f, 0.f);
        if (j < D4) {
            float4 em = er[j];
            float4 a = accs[it];
            int d = j * 4;
            o.x = em.x + fmaxf(a.x + Bias[d + 0], 0.f);
            o.y = em.y + fmaxf(a.y + Bias[d + 1], 0.f);
            o.z = em.z + fmaxf(a.z + Bias[d + 2], 0.f);
            o.w = em.w + fmaxf(a.w + Bias[d + 3], 0.f);
        }
        ho[j] = o;
        float xs[4] = {o.x, o.y, o.z, o.w};
        __nv_bfloat16 h[4], l[4];
#pragma unroll
        for (int q = 0; q < 4; q++) split2(xs[q], h[q], l[q]);
        __nv_bfloat162 h0, h1, l0, l1;
        h0.x = h[0]; h0.y = h[1]; h1.x = h[2]; h1.y = h[3];
        l0.x = l[0]; l0.y = l[1]; l1.x = l[2]; l1.y = l[3];
        ch[2 * j] = h0; ch[2 * j + 1] = h1;
        cl[2 * j] = l0; cl[2 * j + 1] = l1;
    }
}

// ---------------- HMMA GEMM (bf16 split-2): C[M,320] = X @ W ----------------
// mode 0: store fp32 C
// mode 4: highway epilogue, write fp32 C + bf16 splits to Oh/Ol
// mode 5: store bf16(result) to Oh only (t-GEMMs; gathers read bf16)
// mode 6: highway epilogue, write bf16(result) to Oh only (final node GEMM)
#define MMN 160
#define MMK 32
#define MMS 40
#define A_TB (128 * MMS * 2)
#define B_TB (MMN * MMS * 2)
#define MM_STAGE (2 * A_TB + 2 * B_TB)
#define MM_SMEM  (2 * MM_STAGE)
#define MM_CH 10

__device__ __forceinline__ void mm_load_stage(uint32_t sb,
                                              const __nv_bfloat16* Xh, const __nv_bfloat16* Xl,
                                              const __nv_bfloat16* Wh, const __nv_bfloat16* Wl,
                                              int bm, int bn, int M, int k0, int tid) {
#pragma unroll
    for (int q = 0; q < 9; q++) {
        int idx = q * 256 + tid;
        if (idx < 1024) {
            int part = idx >> 9;
            int r = (idx & 511) >> 2, c = idx & 3;
            const __nv_bfloat16* src = (part ? Xl : Xh) + (size_t)(bm + r) * 320 + k0 + c * 8;
            int ok = (bm + r < M) ? 16 : 0;
            cp16(sb + part * A_TB + r * (MMS * 2) + c * 16, src, ok);
        } else if (idx < 2304) {
            int t = idx - 1024;
            int part = t >= 640 ? 1 : 0;
            int rr = t - part * 640;
            int r = rr >> 2, c = rr & 3;
            const __nv_bfloat16* src = (part ? Wl : Wh) + (size_t)(bn + r) * 320 + k0 + c * 8;
            cp16(sb + 2 * A_TB + part * B_TB + r * (MMS * 2) + c * 16, src, 16);
        }
    }
    CP_COMMIT();
}

__global__ __launch_bounds__(256, 2) void mgemm_kernel(const __nv_bfloat16* __restrict__ Xh,
                                                       const __nv_bfloat16* __restrict__ Xl,
                                                       const __nv_bfloat16* __restrict__ Wh,
                                                       const __nv_bfloat16* __restrict__ Wl,
                                                       float* __restrict__ C, int M, int mode,
                                                       const float* __restrict__ ep1,
                                                       const float* __restrict__ ep2,
                                                       const float* __restrict__ epv,
                                                       __nv_bfloat16* __restrict__ Oh,
                                                       __nv_bfloat16* __restrict__ Ol) {
    extern __shared__ char sm8[];
    uint32_t smb = smem_to_u32(sm8);
    int tid = threadIdx.x, wid = tid >> 5, lane = tid & 31;
    int bn = blockIdx.x * MMN, bm = blockIdx.y * 128;
    int wm = (wid >> 1) * 32;
    int wn = (wid & 1) * 80;

    float acc[2][10][4];
#pragma unroll
    for (int i = 0; i < 2; i++)
#pragma unroll
        for (int j = 0; j < 10; j++)
#pragma unroll
            for (int q = 0; q < 4; q++) acc[i][j][q] = 0.f;

    int aRow = lane & 15, aKsel = (lane >> 4) * 8;
    int bRow = (lane >> 4) * 8 + (lane & 7), bKsel = ((lane >> 3) & 1) * 8;

    mm_load_stage(smb, Xh, Xl, Wh, Wl, bm, bn, M, 0, tid);

    for (int ch = 0; ch < MM_CH; ch++) {
        uint32_t sb = smb + (ch & 1) * MM_STAGE;
        if (ch + 1 < MM_CH)
            mm_load_stage(smb + ((ch + 1) & 1) * MM_STAGE, Xh, Xl, Wh, Wl, bm, bn, M, (ch + 1) * MMK, tid);
        if (ch + 1 < MM_CH) cp_wait<1>(); else cp_wait<0>();
        __syncthreads();
#pragma unroll
        for (int ks = 0; ks < 2; ks++) {
            // K = 304 suffices: k >= 304 is provably zero in both operands
            if (ks == 1 && ch == MM_CH - 1) continue;
            int k0 = ks * 16;
            uint32_t ah[2][4], al[2][4];
#pragma unroll
            for (int i = 0; i < 2; i++) {
                uint32_t ad = sb + ((wm + i * 16 + aRow) * MMS + k0 + aKsel) * 2;
                ldsm4(ah[i], ad);
                ldsm4(al[i], ad + A_TB);
            }
#pragma unroll
            for (int j = 0; j < 5; j++) {
                uint32_t bh[4], bl[4];
                uint32_t bd = sb + 2 * A_TB + ((wn + j * 16 + bRow) * MMS + k0 + bKsel) * 2;
                ldsm4(bh, bd);
                ldsm4(bl, bd + B_TB);
#pragma unroll
                for (int i = 0; i < 2; i++)
#pragma unroll
                    for (int t = 0; t < 2; t++) {
                        float* a4 = acc[i][j * 2 + t];
                        mma16816(a4, ah[i], bh[t * 2], bh[t * 2 + 1]);
                        mma16816(a4, ah[i], bl[t * 2], bl[t * 2 + 1]);
                        mma16816(a4, al[i], bh[t * 2], bh[t * 2 + 1]);
                    }
            }
        }
        __syncthreads();
    }

#pragma unroll
    for (int i = 0; i < 2; i++)
#pragma unroll
        for (int jj = 0; jj < 10; jj++) {
            int col = bn + wn + jj * 8 + (lane & 3) * 2;
#pragma unroll
            for (int half = 0; half < 2; half++) {
                int row = bm + wm + i * 16 + (lane >> 2) + half * 8;
                if (row >= M) continue;
                float v0 = acc[i][jj][half * 2], v1 = acc[i][jj][half * 2 + 1];
                if (mode == 0) {
                    *(float2*)(C + (size_t)row * SD + col) = make_float2(v0, v1);
                } else if (mode == 5) {
                    __nv_bfloat162 hh;
                    hh.x = __float2bfloat16_rn(v0);
                    hh.y = __float2bfloat16_rn(v1);
                    *(__nv_bfloat162*)(Oh + (size_t)row * SD + col) = hh;
                } else {
                    const float* l1 = ep1 + (size_t)row * SD + col;
                    const float* gc = ep2 + (size_t)row * SD + col;
                    float2 a = *(const float2*)l1;
                    float2 g = *(const float2*)gc;
                    float o0 = 0.f, o1 = 0.f;
                    if (col < D_N) {
                        float tg = 1.0f / (1.0f + expf(-(v0 + epv[col])));
                        o0 = tg * fmaxf(g.x, 0.f) + (1.0f - tg) * a.x;
                    }
                    if (col + 1 < D_N) {
                        float tg = 1.0f / (1.0f + expf(-(v1 + epv[col + 1])));
                        o1 = tg * fmaxf(g.y, 0.f) + (1.0f - tg) * a.y;
                    }
                    if (mode == 4) {
                        *(float2*)(C + (size_t)row * SD + col) = make_float2(o0, o1);
                        __nv_bfloat16 h0, h1, l0, l1b;
                        split2(o0, h0, l0);
                        split2(o1, h1, l1b);
                        __nv_bfloat162 hh, ll;
                        hh.x = h0; hh.y = h1;
                        ll.x = l0; ll.y = l1b;
                        *(__nv_bfloat162*)(Oh + (size_t)row * SD + col) = hh;
                        *(__nv_bfloat162*)(Ol + (size_t)row * SD + col) = ll;
                    } else {  // mode 6: bf16 node only
                        __nv_bfloat162 hh;
                        hh.x = __float2bfloat16_rn(o0);
                        hh.y = __float2bfloat16_rn(o1);
                        *(__nv_bfloat162*)(Oh + (size_t)row * SD + col) = hh;
                    }
                }
            }
        }
}

// ---------------- FFMA2 SGEMM (small R_N GEMMs) ----------------
#define BM 256
#define BN 64
#define BK 16
#define KTILES 19
__global__ __launch_bounds__(256, 2) void sgemm_kernel(const float* __restrict__ A,
                                                       const float* __restrict__ B,
                                                       float* __restrict__ C,
                                                       int M, int accumulate) {
    __shared__ float As[2][BK][BM];
    __shared__ float Bs[2][BK][BN];
    int bm = blockIdx.y * BM;
    int bn = blockIdx.x * BN;
    int tid = threadIdx.x;
    int tx = tid & 7;
    int ty = tid >> 3;
    int arow = bm + tid;
    bool avalid = arow < M;
    const float* Aptr = A + (size_t)arow * SD;
    int brow  = tid >> 4;
    int bcol4 = tid & 15;
    const float* Bptr = B + (size_t)brow * SD + bn + bcol4 * 4;

    unsigned long long acc[8][4];
#pragma unroll
    for (int i = 0; i < 8; i++)
#pragma unroll
        for (int j = 0; j < 4; j++) acc[i][j] = 0ull;

    float4 ra[4], rb;
#pragma unroll
    for (int c = 0; c < 4; c++)
        ra[c] = avalid ? *(const float4*)(Aptr + c * 4) : make_float4(0.f, 0.f, 0.f, 0.f);
    rb = *(const float4*)(Bptr);
#pragma unroll
    for (int c = 0; c < 4; c++) {
        As[0][c * 4 + 0][tid] = ra[c].x;
        As[0][c * 4 + 1][tid] = ra[c].y;
        As[0][c * 4 + 2][tid] = ra[c].z;
        As[0][c * 4 + 3][tid] = ra[c].w;
    }
    *(float4*)(&Bs[0][brow][bcol4 * 4]) = rb;
    __syncthreads();

    for (int t = 0; t < KTILES; t++) {
        int cur = t & 1, nxt = cur ^ 1;
        if (t + 1 < KTILES) {
            int k0 = (t + 1) * BK;
#pragma unroll
            for (int c = 0; c < 4; c++)
                ra[c] = avalid ? *(const float4*)(Aptr + k0 + c * 4) : make_float4(0.f, 0.f, 0.f, 0.f);
            rb = *(const float4*)(Bptr + (size_t)k0 * SD);
        }
#pragma unroll
        for (int k = 0; k < BK; k++) {
            ulonglong2 bb0 = *(const ulonglong2*)(&Bs[cur][k][tx * 8]);
            ulonglong2 bb1 = *(const ulonglong2*)(&Bs[cur][k][tx * 8 + 4]);
            unsigned long long b2[4] = {bb0.x, bb0.y, bb1.x, bb1.y};
            float4 a0 = *(const float4*)(&As[cur][k][ty * 8]);
            float4 a1 = *(const float4*)(&As[cur][k][ty * 8 + 4]);
            unsigned long long a2[8];
            a2[0] = bcast2(a0.x); a2[1] = bcast2(a0.y); a2[2] = bcast2(a0.z); a2[3] = bcast2(a0.w);
            a2[4] = bcast2(a1.x); a2[5] = bcast2(a1.y); a2[6] = bcast2(a1.z); a2[7] = bcast2(a1.w);
#pragma unroll
            for (int i = 0; i < 8; i++)
#pragma unroll
                for (int j = 0; j < 4; j++)
                    ffma2(acc[i][j], a2[i], b2[j]);
        }
        if (t + 1 < KTILES) {
#pragma unroll
            for (int c = 0; c < 4; c++) {
                As[nxt][c * 4 + 0][tid] = ra[c].x;
                As[nxt][c * 4 + 1][tid] = ra[c].y;
                As[nxt][c * 4 + 2][tid] = ra[c].z;
                As[nxt][c * 4 + 3][tid] = ra[c].w;
            }
            *(float4*)(&Bs[nxt][brow][bcol4 * 4]) = rb;
        }
        __syncthreads();
    }

    int gcol = bn + tx * 8;
#pragma unroll
    for (int i = 0; i < 8; i++) {
        int grow = bm + ty * 8 + i;
        if (grow >= M) continue;
        float2 u0 = unpack2(acc[i][0]);
        float2 u1 = unpack2(acc[i][1]);
        float2 u2 = unpack2(acc[i][2]);
        float2 u3 = unpack2(acc[i][3]);
        float* crow = C + (size_t)grow * SD + gcol;
        if (accumulate) {
            float4 c0 = *(float4*)crow;
            float4 c1 = *(float4*)(crow + 4);
            *(float4*)crow       = make_float4(c0.x + u0.x, c0.y + u0.y, c0.z + u1.x, c0.w + u1.y);
            *(float4*)(crow + 4) = make_float4(c1.x + u2.x, c1.y + u2.y, c1.z + u3.x, c1.w + u3.y);
        } else {
            *(float4*)crow       = make_float4(u0.x, u0.y, u1.x, u1.y);
            *(float4*)(crow + 4) = make_float4(u2.x, u2.y, u3.x, u3.y);
        }
    }
}

// Fused hinge loss over bf16 node: one block per pair t.
__global__ __launch_bounds__(256) void loss_kernel(const int* __restrict__ pl,
                                                   const int* __restrict__ pr,
                                                   const int* __restrict__ nr,
                                                   const int* __restrict__ nl,
                                                   const float* __restrict__ mask,
                                                   const __nv_bfloat16* __restrict__ node,
                                                   float* __restrict__ out) {
    __shared__ float4 sl[D4], sr[D4];
    __shared__ float wpart[8];
    __shared__ float s_dm;
    int t    = blockIdx.x;
    int tid  = threadIdx.x;
    int lane = tid & 31;
    int wid  = tid >> 5;

    const uint2* xl = (const uint2*)(node + (size_t)pl[t] * SD);
    const uint2* xr = (const uint2*)(node + (size_t)pr[t] * SD);
    float d = 0.f;
    if (tid < D4) {
        uint2 ua = xl[tid], ub = xr[tid];
        float2 a0 = bf2f2(ua.x), a1 = bf2f2(ua.y);
        float2 b0 = bf2f2(ub.x), b1 = bf2f2(ub.y);
        float4 a = make_float4(a0.x, a0.y, a1.x, a1.y);
        float4 b = make_float4(b0.x, b0.y, b1.x, b1.y);
        sl[tid] = a; sr[tid] = b;
        d = fabsf(a.x - b.x) + fabsf(a.y - b.y) + fabsf(a.z - b.z) + fabsf(a.w - b.w);
    }
    d = warp_sum(d);
    if (lane == 0) wpart[wid] = d;
    __syncthreads();
    if (tid == 0) s_dm = wpart[0] + wpart[1] + wpart[2] + GAMMA_F;
    __syncthreads();
    float dm = s_dm;

    float hsum = 0.f;
    for (int k = wid; k < K_N; k += 8) {
        int i = t * K_N + k;
        const uint2* xR = (const uint2*)(node + (size_t)nr[i] * SD);
        const uint2* xL = (const uint2*)(node + (size_t)nl[i] * SD);
        float s1 = 0.f, s2 = 0.f;
#pragma unroll
        for (int it = 0; it < 3; it++) {
            int j = lane + it * 32;
            if (j < D4) {
                float4 a = sl[j], b = sr[j];
                uint2 uR = xR[j], uL = xL[j];
                float2 c0 = bf2f2(uR.x), c1 = bf2f2(uR.y);
                float2 d0 = bf2f2(uL.x), d1 = bf2f2(uL.y);
                s1 += fabsf(a.x - c0.x) + fabsf(a.y - c0.y) + fabsf(a.z - c1.x) + fabsf(a.w - c1.y);
                s2 += fabsf(d0.x - b.x) + fabsf(d0.y - b.y) + fabsf(d1.x - b.z) + fabsf(d1.y - b.w);
            }
        }
        s1 = warp_sum(s1);
        s2 = warp_sum(s2);
        if (lane == 0) hsum += (fmaxf(dm - s1, 0.f) + fmaxf(dm - s2, 0.f)) * mask[i];
    }
    if (lane == 0) wpart[wid] = hsum;
    __syncthreads();
    if (tid == 0) {
        float tot = 0.f;
#pragma unroll
        for (int w = 0; w < 8; w++) tot += wpart[w];
        atomicAdd(out, tot * 0.5f);
    }
}

// ---------------- host ----------------
extern "C" void kernel_launch(void* const* d_in, const int* in_sizes, int n_in,
                              void* d_out, int out_size) {
    const float* we    = (const float*)d_in[0];
    const float* kgw   = (const float*)d_in[1];
    const float* bg    = (const float*)d_in[2];
    const float* W1    = (const float*)d_in[3];
    const float* W2    = (const float*)d_in[4];
    const float* Dense = (const float*)d_in[5];
    const float* Bias  = (const float*)d_in[6];
    const int*   hr_rows = (const int*)d_in[7];
    const int*   hr_cols = (const int*)d_in[8];
    const float* hr_vals = (const float*)d_in[9];
    const int*   tr_rows = (const int*)d_in[10];
    const int*   tr_cols = (const int*)d_in[11];
    const float* tr_vals = (const float*)d_in[12];
    const int*   er_rows = (const int*)d_in[13];
    const int*   er_cols = (const int*)d_in[14];
    const float* er_vals = (const float*)d_in[15];
    const int*   adj_rows = (const int*)d_in[16];
    const int*   adj_cols = (const int*)d_in[17];
    const float* adj_vals = (const float*)d_in[18];
    const int*   pos_left  = (const int*)d_in[19];
    const int*   pos_right = (const int*)d_in[20];
    const int*   neg_right = (const int*)d_in[21];
    const int*   neg_left  = (const int*)d_in[22];
    const float* mask      = (const float*)d_in[23];
    float* out = (float*)d_out;

    int nnz_hr  = in_sizes[7];
    int nnz_tr  = in_sizes[10];
    int nnz_er  = in_sizes[13];
    int nnz_adj = in_sizes[16];

    float *p_emb, *p_A1, *p_A2, *p_A3, *p_A5, *p_A6, *p_Lm, *p_Rm, *p_P, *p_Wt;
    __nv_bfloat16 *p_Bh, *p_Bl, *p_Ch, *p_Cl, *p_WTh, *p_WTl;
    int *p_adj_ptr, *p_adj_cur, *p_adj_c, *p_er_ptr, *p_er_cur, *p_er_c, *p_bsum;
    float *p_adj_v, *p_er_v;
    cudaGetSymbolAddress((void**)&p_emb, g_emb);
    cudaGetSymbolAddress((void**)&p_A1,  g_A1);
    cudaGetSymbolAddress((void**)&p_A2,  g_A2);
    cudaGetSymbolAddress((void**)&p_A3,  g_A3);
    cudaGetSymbolAddress((void**)&p_A5,  g_A5);
    cudaGetSymbolAddress((void**)&p_A6,  g_A6);
    cudaGetSymbolAddress((void**)&p_Lm,  g_Lm);
    cudaGetSymbolAddress((void**)&p_Rm,  g_Rm);
    cudaGetSymbolAddress((void**)&p_P,   g_P);
    cudaGetSymbolAddress((void**)&p_Wt,  g_Wt);
    cudaGetSymbolAddress((void**)&p_Bh,  g_Bh);
    cudaGetSymbolAddress((void**)&p_Bl,  g_Bl);
    cudaGetSymbolAddress((void**)&p_Ch,  g_Ch);
    cudaGetSymbolAddress((void**)&p_Cl,  g_Cl);
    cudaGetSymbolAddress((void**)&p_WTh, g_WTh);
    cudaGetSymbolAddress((void**)&p_WTl, g_WTl);
    cudaGetSymbolAddress((void**)&p_adj_ptr, g_adj_ptr);
    cudaGetSymbolAddress((void**)&p_adj_cur, g_adj_cur);
    cudaGetSymbolAddress((void**)&p_adj_c,   g_adj_c);
    cudaGetSymbolAddress((void**)&p_adj_v,   g_adj_v);
    cudaGetSymbolAddress((void**)&p_er_ptr,  g_er_ptr);
    cudaGetSymbolAddress((void**)&p_er_cur,  g_er_cur);
    cudaGetSymbolAddress((void**)&p_er_c,    g_er_c);
    cudaGetSymbolAddress((void**)&p_er_v,    g_er_v);
    cudaGetSymbolAddress((void**)&p_bsum,    g_bsum);

    __nv_bfloat16* p_A3b = (__nv_bfloat16*)p_A3;   // t-GEMM bf16 output buffer

    cudaFuncSetAttribute(mgemm_kernel, cudaFuncAttributeMaxDynamicSharedMemorySize, MM_SMEM);

    dim3 mmGrid(SD / MMN, (E_N + 127) / 128);       // (2, 782)
    dim3 gemmGridR(SD / BN, (R_N + BM - 1) / BM);
    const int NB_E = (E_N + 1023) / 1024;           // 98
    const int GW = (E_N * 32 + 255) / 256;          // warp-per-row grids

    // 1-3, then launch #4 = first HMMA GEMM (profiled)
    wsplit_kernel<<<(4 * WOFF + 255) / 256, 256>>>(Dense, W1, W2, kgw);
    normalize_kernel<<<GW, 256>>>(we);
    zero4_kernel<<<(R_N * SD / 4 + 255) / 256, 256>>>((float4*)p_Lm, R_N * SD / 4);
    mgemm_kernel<<<mmGrid, 256, MM_SMEM>>>(p_Bh, p_Bl, p_WTh, p_WTl, p_A1, E_N, 0, 0, 0, 0, 0, 0);

    // ---- CSR build: adj ----
    zcnt_kernel<<<(E_N + 255) / 256, 256>>>(p_adj_cur, E_N);
    hist_kernel<<<(nnz_adj + 255) / 256, 256>>>(adj_rows, nnz_adj, p_adj_cur);
    scan1_kernel<<<NB_E, 256>>>(p_adj_cur, E_N, p_bsum);
    scan2_kernel<<<1, 32>>>(p_bsum, NB_E);
    scan3_kernel<<<NB_E, 256>>>(p_adj_cur, p_bsum, E_N, p_adj_ptr, p_adj_cur);
    scatter_kernel<<<(nnz_adj + 255) / 256, 256>>>(adj_rows, adj_cols, adj_vals, nnz_adj,
                                                   p_adj_cur, p_adj_c, p_adj_v);

    // ---- CSR build: er ----
    zcnt_kernel<<<(E_N + 255) / 256, 256>>>(p_er_cur, E_N);
    hist_kernel<<<(nnz_er + 255) / 256, 256>>>(er_rows, nnz_er, p_er_cur);
    scan1_kernel<<<NB_E, 256>>>(p_er_cur, E_N, p_bsum);
    scan2_kernel<<<1, 32>>>(p_bsum, NB_E);
    scan3_kernel<<<NB_E, 256>>>(p_er_cur, p_bsum, E_N, p_er_ptr, p_er_cur);
    scatter_kernel<<<(nnz_er + 255) / 256, 256>>>(er_rows, er_cols, er_vals, nnz_er,
                                                  p_er_cur, p_er_c, p_er_v);

    // relation aggregation (scatter; small outputs)
    zero4_kernel<<<(R_N * SD / 4 + 255) / 256, 256>>>((float4*)p_Rm, R_N * SD / 4);
    spmm_kernel<<<(nnz_hr + 7) / 8, 256>>>(hr_rows, hr_cols, hr_vals, nnz_hr, p_emb, p_Lm);
    spmm_kernel<<<(nnz_tr + 7) / 8, 256>>>(tr_rows, tr_cols, tr_vals, nnz_tr, p_emb, p_Rm);

    // P = L @ Db1 + Rm @ Db2
    pad_weights_kernel<<<(2 * SD * SD + 255) / 256, 256>>>(Dense);
    sgemm_kernel<<<gemmGridR, 256>>>(p_Lm, p_Wt, p_P, R_N, 0);
    sgemm_kernel<<<gemmGridR, 256>>>(p_Rm, p_Wt + SD * SD, p_P, R_N, 1);

    zero_out_kernel<<<1, 1>>>(out);

    // h = emb + relu(A1 + er_gather + Bias) -> A2, splits -> Ch/Cl (fused)
    h_er_kernel<<<GW, 256>>>(p_er_ptr, p_er_c, p_er_v, Bias);

    // layer 1: t1 = h@W1 -> A3 (bf16); gcn1 gather -> A5; gate GEMM fuses highway -> A6 (+ splits -> Bh/Bl)
    mgemm_kernel<<<mmGrid, 256, MM_SMEM>>>(p_Ch, p_Cl, p_WTh + 1 * WOFF, p_WTl + 1 * WOFF, p_A1, E_N, 5, 0, 0, 0, p_A3b, 0);
    gspmm_kernel<<<GW, 256>>>(p_adj_ptr, p_adj_c, p_adj_v, p_A3b, p_A5, E_N);
    mgemm_kernel<<<mmGrid, 256, MM_SMEM>>>(p_Ch, p_Cl, p_WTh + 3 * WOFF, p_WTl + 3 * WOFF, p_A6, E_N, 4, p_A2, p_A5, bg, p_Bh, p_Bl);

    // layer 2: t2 = hg1@W2 -> A3 (bf16); gcn2 gather -> A1; gate GEMM fuses highway -> node bf16 (Ch)
    mgemm_kernel<<<mmGrid, 256, MM_SMEM>>>(p_Bh, p_Bl, p_WTh + 2 * WOFF, p_WTl + 2 * WOFF, p_A1, E_N, 5, 0, 0, 0, p_A3b, 0);
    gspmm_kernel<<<GW, 256>>>(p_adj_ptr, p_adj_c, p_adj_v, p_A3b, p_A1, E_N);
    mgemm_kernel<<<mmGrid, 256, MM_SMEM>>>(p_Bh, p_Bl, p_WTh + 3 * WOFF, p_WTl + 3 * WOFF, p_A2, E_N, 6, p_A6, p_A1, bg, p_Ch, 0);

    // fused loss over bf16 node
    loss_kernel<<<T_N, 256>>>(pos_left, pos_right, neg_right, neg_left, mask, p_Ch, out);
    (void)n_in; (void)out_size;
}